// round 10
// baseline (speedup 1.0000x reference)
#include <cuda_runtime.h>
#include <cuda_bf16.h>
#include <cstddef>

#define BATCH 256
#define SEQ   512
#define DIN   64
#define HID   512
#define GRIDN 128
#define NTH   256

#define TM 64
#define TN 64
#define KA_PER 144          // 576 / 4
#define KB_PER 256          // 1024 / 4

#define SA 152              // A-phase row stride (bf16 elems)
#define SB 264              // B-phase row stride

#define OFF_WA_HI 0
#define OFF_WA_LO (OFF_WA_HI + 64 * SA)
#define OFF_AA_HI (OFF_WA_LO + 64 * SA)
#define OFF_AA_LO (OFF_AA_HI + 64 * SA)
#define OFF_WB_HI (OFF_AA_LO + 64 * SA)
#define OFF_WB_LO (OFF_WB_HI + 64 * SB)
#define OFF_AB_HI (OFF_WB_LO + 64 * SB)
#define OFF_AB_LO (OFF_AB_HI + 64 * SB)
#define ELEMS_TOT (OFF_AB_LO + 64 * SB)          // 106,496 bf16 = 212,992 B
#define SCR_STRIDE 68                            // fp32 scr row stride (17,408 B region)
#define SMEM_BYTES (ELEMS_TOT * 2 + 64)          // + mbarrier region

typedef unsigned long long ull;

// ---------------- cross-CTA state ----------------
__device__ __nv_bfloat16 g_Xhi[BATCH * SEQ * DIN];
__device__ __nv_bfloat16 g_Xlo[BATCH * SEQ * DIN];
__device__ __nv_bfloat16 g_H1hi[2][BATCH * HID], g_H1lo[2][BATCH * HID];
__device__ __nv_bfloat16 g_H2hi[2][BATCH * HID], g_H2lo[2][BATCH * HID];

struct __align__(128) Line { unsigned v; unsigned pad[31]; };
__device__ Line g_leaf[8];
__device__ Line g_root;
__device__ Line g_gen;
__device__ Line g_gcnt[4];
__device__ Line g_ggen[4];

__device__ __forceinline__ void grid_sync_init(int leaf) {
    __syncthreads();
    if (threadIdx.x == 0) {
        unsigned gen = *(volatile unsigned*)&g_gen.v;
        __threadfence();
        if (atomicAdd(&g_leaf[leaf].v, 1u) == 15u) {
            g_leaf[leaf].v = 0u;
            __threadfence();
            if (atomicAdd(&g_root.v, 1u) == 7u) {
                g_root.v = 0u;
                __threadfence();
                *(volatile unsigned*)&g_gen.v = gen + 1u;
            } else {
                while (*(volatile unsigned*)&g_gen.v == gen) __nanosleep(16);
            }
        } else {
            while (*(volatile unsigned*)&g_gen.v == gen) __nanosleep(16);
        }
        __threadfence();
    }
    __syncthreads();
}

__device__ __forceinline__ void group_bar(int grp) {
    __syncthreads();
    if (threadIdx.x == 0) {
        unsigned gen = *(volatile unsigned*)&g_ggen[grp].v;
        __threadfence();
        if (atomicAdd(&g_gcnt[grp].v, 1u) == 31u) {
            g_gcnt[grp].v = 0u;
            __threadfence();
            *(volatile unsigned*)&g_ggen[grp].v = gen + 1u;
        } else {
            while (*(volatile unsigned*)&g_ggen[grp].v == gen) __nanosleep(16);
        }
        __threadfence();
    }
    __syncthreads();
}

#define CLUSTER_SYNC() do { \
    asm volatile("barrier.cluster.arrive.aligned;" ::: "memory"); \
    asm volatile("barrier.cluster.wait.aligned;" ::: "memory"); \
} while (0)

#define NAMED_BAR(id) asm volatile("bar.sync %0, 128;" :: "r"(id) : "memory")

#define MBARRIER_INIT(addr, cnt) \
    asm volatile("mbarrier.init.shared.b64 [%0], %1;" :: "r"(addr), "r"(cnt) : "memory")

// arrive on CTA `rank`'s mbarrier at the same smem offset (release, cluster scope)
#define MBAR_ARRIVE_RANK(local_addr, rank) \
    asm volatile("{\n\t.reg .b32 ra;\n\t" \
        "mapa.shared::cluster.u32 ra, %0, %1;\n\t" \
        "mbarrier.arrive.release.cluster.shared::cluster.b64 _, [ra];\n\t}" \
        :: "r"(local_addr), "r"(rank) : "memory")

#define MBAR_WAIT_CLUSTER(mbar, parity) do { \
    unsigned _d; \
    do { \
        asm volatile("{\n\t.reg .pred P;\n\t" \
            "mbarrier.try_wait.parity.acquire.cluster.shared::cta.b64 P, [%1], %2, 0x989680;\n\t" \
            "selp.b32 %0, 1, 0, P;\n\t}" \
            : "=r"(_d) : "r"(mbar), "r"(parity) : "memory"); \
    } while (!_d); \
} while (0)

__device__ __forceinline__ unsigned mapa_rank(unsigned smaddr, unsigned rank) {
    unsigned r;
    asm("mapa.shared::cluster.u32 %0, %1, %2;" : "=r"(r) : "r"(smaddr), "r"(rank));
    return r;
}
__device__ __forceinline__ float4 ld_dsmem_f4(unsigned addr) {
    float4 v;
    asm volatile("ld.shared::cluster.v4.f32 {%0,%1,%2,%3}, [%4];"
                 : "=f"(v.x), "=f"(v.y), "=f"(v.z), "=f"(v.w) : "r"(addr));
    return v;
}

__device__ __forceinline__ void mma16816(float* c, const unsigned* a, const unsigned* b) {
    asm volatile(
        "mma.sync.aligned.m16n8k16.row.col.f32.bf16.bf16.f32 "
        "{%0,%1,%2,%3}, {%4,%5,%6,%7}, {%8,%9}, {%0,%1,%2,%3};"
        : "+f"(c[0]), "+f"(c[1]), "+f"(c[2]), "+f"(c[3])
        : "r"(a[0]), "r"(a[1]), "r"(a[2]), "r"(a[3]), "r"(b[0]), "r"(b[1]));
}

#define CP16(dst_u32, src_ptr) \
    asm volatile("cp.async.cg.shared.global [%0], [%1], 16;" \
                 :: "r"(dst_u32), "l"(src_ptr))
#define CP_COMMIT() asm volatile("cp.async.commit_group;")
#define CP_WAIT(n)  asm volatile("cp.async.wait_group %0;" :: "n"(n))

__device__ __forceinline__ void split_bf16(float v, __nv_bfloat16& hi, __nv_bfloat16& lo) {
    hi = __float2bfloat16_rn(v);
    lo = __float2bfloat16_rn(v - __bfloat162float(hi));
}

__global__ void __launch_bounds__(NTH, 1) __cluster_dims__(4, 1, 1) rnn_hmma(
    const float* __restrict__ x,
    const float* __restrict__ W_ih0, const float* __restrict__ W_hh0,
    const float* __restrict__ b_ih0, const float* __restrict__ b_hh0,
    const float* __restrict__ W_ih1, const float* __restrict__ W_hh1,
    const float* __restrict__ b_ih1, const float* __restrict__ b_hh1,
    const float* __restrict__ W_fc,  const float* __restrict__ b_fc,
    float* __restrict__ out)
{
    const int tid  = threadIdx.x;
    const int bid  = blockIdx.x;
    const int leaf = bid & 7;
    const int grp  = bid >> 5;
    const int ks   = bid & 3;
    const int tile = bid >> 2;
    const int mt   = tile >> 3;
    const int nt   = tile & 7;
    const int m0   = mt * TM;
    const int n0   = nt * TN;

    extern __shared__ __nv_bfloat16 sm[];
    const unsigned sm_u32 = (unsigned)__cvta_generic_to_shared(sm);
    // scrA aliases AA staging; scrB aliases AB staging (both dead after their compute)
    float* scrA = (float*)(sm + OFF_AA_HI);
    float* scrB = (float*)(sm + OFF_AB_HI);
    const unsigned scrA_u32 = sm_u32 + OFF_AA_HI * 2;
    const unsigned scrB_u32 = sm_u32 + OFF_AB_HI * 2;
    const unsigned mbA = sm_u32 + ELEMS_TOT * 2;
    const unsigned mbB = mbA + 16;

    // ---------- one-time: split weight slices -> SMEM ----------
    {
        const int kb = ks * KA_PER;
        for (int idx = tid; idx < 64 * KA_PER; idx += NTH) {
            int n = idx / KA_PER, k = idx - n * KA_PER;
            int kg = kb + k;
            float v = (kg < DIN) ? W_ih0[(n0 + n) * DIN + kg]
                                 : W_hh0[(n0 + n) * HID + (kg - DIN)];
            __nv_bfloat16 hi, lo; split_bf16(v, hi, lo);
            sm[OFF_WA_HI + n * SA + k] = hi;
            sm[OFF_WA_LO + n * SA + k] = lo;
        }
        const int kbb = ks * KB_PER;
        for (int idx = tid; idx < 64 * KB_PER; idx += NTH) {
            int n = idx / KB_PER, k = idx - n * KB_PER;
            int kg = kbb + k;
            float v = (kg < HID) ? W_ih1[(n0 + n) * HID + kg]
                                 : W_hh1[(n0 + n) * HID + (kg - HID)];
            __nv_bfloat16 hi, lo; split_bf16(v, hi, lo);
            sm[OFF_WB_HI + n * SB + k] = hi;
            sm[OFF_WB_LO + n * SB + k] = lo;
        }
    }
    // ---------- one-time: pre-split x ----------
    {
        const int total = BATCH * SEQ * DIN;
        for (int i = (bid * NTH + tid) * 4; i < total; i += GRIDN * NTH * 4) {
            float4 v = *(const float4*)(x + i);
            __nv_bfloat16 h0,h1,h2,h3,l0,l1,l2,l3;
            split_bf16(v.x,h0,l0); split_bf16(v.y,h1,l1);
            split_bf16(v.z,h2,l2); split_bf16(v.w,h3,l3);
            *(__nv_bfloat162*)(g_Xhi + i)     = __halves2bfloat162(h0, h1);
            *(__nv_bfloat162*)(g_Xhi + i + 2) = __halves2bfloat162(h2, h3);
            *(__nv_bfloat162*)(g_Xlo + i)     = __halves2bfloat162(l0, l1);
            *(__nv_bfloat162*)(g_Xlo + i + 2) = __halves2bfloat162(l2, l3);
        }
    }
    // ---------- zero t=-1 states ----------
    {
        const int per = (BATCH * HID) / GRIDN;
        const int base = bid * per;
        __nv_bfloat162 z = __halves2bfloat162(__float2bfloat16(0.f), __float2bfloat16(0.f));
        for (int i = tid * 2; i < per; i += NTH * 2) {
            *(__nv_bfloat162*)(&g_H1hi[1][base + i]) = z;
            *(__nv_bfloat162*)(&g_H1lo[1][base + i]) = z;
            *(__nv_bfloat162*)(&g_H2hi[1][base + i]) = z;
            *(__nv_bfloat162*)(&g_H2lo[1][base + i]) = z;
        }
    }
    if (tid == 0) {
        MBARRIER_INIT(mbA, 4);
        MBARRIER_INIT(mbB, 4);
    }
    __syncthreads();
    CLUSTER_SYNC();           // mbarrier inits visible cluster-wide
    grid_sync_init(leaf);

    // ---------- roles ----------
    const int lane  = tid & 31;
    const int wid   = tid >> 5;
    const bool isA  = (wid < 4);
    const int cwid  = isA ? wid : wid - 4;
    const int wm    = cwid & 1;
    const int wn    = (cwid >> 1) & 1;
    const int q     = lane >> 2;
    const int tg2   = (lane & 3) * 2;

    const int lt    = isA ? tid : tid - 128;   // 0..127 within warp-group
    const int s_row = lt >> 1;                 // staging row
    const int s_half= lt & 1;

    // reduce role (per warp-group: 512 cluster threads, 2 quads each)
    const int ccr = (lt & 15) << 2;
    float4 biasA, biasB;
    {
        float4 bi = *(const float4*)(b_ih0 + n0 + ccr);
        float4 bh = *(const float4*)(b_hh0 + n0 + ccr);
        biasA = make_float4(bi.x+bh.x, bi.y+bh.y, bi.z+bh.z, bi.w+bh.w);
        bi = *(const float4*)(b_ih1 + n0 + ccr);
        bh = *(const float4*)(b_hh1 + n0 + ccr);
        biasB = make_float4(bi.x+bh.x, bi.y+bh.y, bi.z+bh.z, bi.w+bh.w);
    }

    // ---------- staging (warp-group local) ----------
    auto stageA_ws = [&](int t, const __nv_bfloat16* h1phi, const __nv_bfloat16* h1plo) {
        const int mgr = m0 + s_row;
        #pragma unroll
        for (int j = 0; j < 9; ++j) {
            int kl = s_half * 72 + j * 8;
            int kg = ks * KA_PER + kl;
            const __nv_bfloat16 *ph, *pl;
            if (kg < DIN) {
                size_t off = (size_t)mgr * (SEQ * DIN) + (size_t)t * DIN + kg;
                ph = g_Xhi + off; pl = g_Xlo + off;
            } else {
                size_t off = (size_t)mgr * HID + (kg - DIN);
                ph = h1phi + off; pl = h1plo + off;
            }
            CP16(sm_u32 + (OFF_AA_HI + s_row * SA + kl) * 2, ph);
            CP16(sm_u32 + (OFF_AA_LO + s_row * SA + kl) * 2, pl);
        }
        CP_COMMIT();
    };
    auto stageB_ws = [&](const __nv_bfloat16* h1phi, const __nv_bfloat16* h1plo,
                         const __nv_bfloat16* h2phi, const __nv_bfloat16* h2plo) {
        const int basecol = (ks < 2) ? ks * KB_PER : ks * KB_PER - HID;
        const __nv_bfloat16* shi = (ks < 2) ? h1phi : h2phi;
        const __nv_bfloat16* slo = (ks < 2) ? h1plo : h2plo;
        size_t roff = (size_t)(m0 + s_row) * HID + basecol;
        #pragma unroll
        for (int j = 0; j < 16; ++j) {
            int kl = s_half * 128 + j * 8;
            CP16(sm_u32 + (OFF_AB_HI + s_row * SB + kl) * 2, shi + roff + kl);
            CP16(sm_u32 + (OFF_AB_LO + s_row * SB + kl) * 2, slo + roff + kl);
        }
        CP_COMMIT();
    };

    // ---------- GEMM: full-K 3-split HMMA on 4 warps (2m x 2n) ----------
    auto computeWS = [&](int offWhi, int offWlo, int offAhi, int offAlo, int st,
                         int kstN, float* __restrict__ scrp, int barid) {
        float acc[2][4][4];
        #pragma unroll
        for (int f = 0; f < 2; f++)
            #pragma unroll
            for (int g = 0; g < 4; g++)
                #pragma unroll
                for (int i = 0; i < 4; i++) acc[f][g][i] = 0.f;

        const __nv_bfloat16* Ah = sm + offAhi;
        const __nv_bfloat16* Al = sm + offAlo;
        const __nv_bfloat16* Wh = sm + offWhi;
        const __nv_bfloat16* Wl = sm + offWlo;
        const int r00 = wm * 32 + q;

        for (int kst = 0; kst < kstN; ++kst) {
            const int kb = kst * 16 + tg2;
            unsigned ah[2][4], al[2][4], bh[4][2], bl[4][2];
            #pragma unroll
            for (int f = 0; f < 2; f++) {
                int r = (r00 + f * 16) * st;
                ah[f][0] = *(const unsigned*)(Ah + r + kb);
                ah[f][1] = *(const unsigned*)(Ah + r + 8 * st + kb);
                ah[f][2] = *(const unsigned*)(Ah + r + kb + 8);
                ah[f][3] = *(const unsigned*)(Ah + r + 8 * st + kb + 8);
                al[f][0] = *(const unsigned*)(Al + r + kb);
                al[f][1] = *(const unsigned*)(Al + r + 8 * st + kb);
                al[f][2] = *(const unsigned*)(Al + r + kb + 8);
                al[f][3] = *(const unsigned*)(Al + r + 8 * st + kb + 8);
            }
            #pragma unroll
            for (int g = 0; g < 4; g++) {
                int nr = (wn * 32 + g * 8 + q) * st;
                bh[g][0] = *(const unsigned*)(Wh + nr + kb);
                bh[g][1] = *(const unsigned*)(Wh + nr + kb + 8);
                bl[g][0] = *(const unsigned*)(Wl + nr + kb);
                bl[g][1] = *(const unsigned*)(Wl + nr + kb + 8);
            }
            #pragma unroll
            for (int f = 0; f < 2; f++)
                #pragma unroll
                for (int g = 0; g < 4; g++) {
                    mma16816(acc[f][g], ah[f], bh[g]);
                    mma16816(acc[f][g], al[f], bh[g]);
                    mma16816(acc[f][g], ah[f], bl[g]);
                }
        }
        NAMED_BAR(barid);         // group warps done reading staged A (scr aliases it)
        #pragma unroll
        for (int f = 0; f < 2; f++)
            #pragma unroll
            for (int g = 0; g < 4; g++) {
                int r = wm * 32 + f * 16 + q;
                int c = wn * 32 + g * 8 + tg2;
                *(float2*)(scrp + r * SCR_STRIDE + c) =
                    make_float2(acc[f][g][0], acc[f][g][1]);
                *(float2*)(scrp + (r + 8) * SCR_STRIDE + c) =
                    make_float2(acc[f][g][2], acc[f][g][3]);
            }
        NAMED_BAR(barid);         // scr stores done
    };

    // ---------- cluster reduce (2 quads per thread) ----------
    auto reduceWS = [&](unsigned scr_base, const float4& bias,
                        __nv_bfloat16* __restrict__ dhi, __nv_bfloat16* __restrict__ dlo) {
        const int gq = ks * 128 + lt;
        #pragma unroll
        for (int h = 0; h < 2; ++h) {
            int qd = gq + h * 512;
            int rr = qd >> 4;
            unsigned a = scr_base + (unsigned)(rr * SCR_STRIDE + ccr) * 4u;
            float4 p0 = ld_dsmem_f4(mapa_rank(a, 0));
            float4 p1 = ld_dsmem_f4(mapa_rank(a, 1));
            float4 p2 = ld_dsmem_f4(mapa_rank(a, 2));
            float4 p3 = ld_dsmem_f4(mapa_rank(a, 3));
            float4 s;
            s.x = bias.x + p0.x + p1.x + p2.x + p3.x;
            s.y = bias.y + p0.y + p1.y + p2.y + p3.y;
            s.z = bias.z + p0.z + p1.z + p2.z + p3.z;
            s.w = bias.w + p0.w + p1.w + p2.w + p3.w;
            float h0 = tanhf(s.x), h1 = tanhf(s.y), h2 = tanhf(s.z), h3 = tanhf(s.w);
            __nv_bfloat16 hi0,hi1,hi2,hi3, lo0,lo1,lo2,lo3;
            split_bf16(h0,hi0,lo0); split_bf16(h1,hi1,lo1);
            split_bf16(h2,hi2,lo2); split_bf16(h3,hi3,lo3);
            __nv_bfloat162 ph0 = __halves2bfloat162(hi0,hi1), ph1 = __halves2bfloat162(hi2,hi3);
            __nv_bfloat162 pl0 = __halves2bfloat162(lo0,lo1), pl1 = __halves2bfloat162(lo2,lo3);
            uint2 uh, ul;
            uh.x = *(unsigned*)&ph0; uh.y = *(unsigned*)&ph1;
            ul.x = *(unsigned*)&pl0; ul.y = *(unsigned*)&pl1;
            size_t doff = (size_t)(m0 + rr) * HID + n0 + ccr;
            __stcg((uint2*)(dhi + doff), uh);
            __stcg((uint2*)(dlo + doff), ul);
        }
    };

    int phA = 0, phB = 0;

    // ============================ main loop: A ∥ B ============================
    for (int t = 0; t < SEQ; ++t) {
        const int pp = (t + 1) & 1, pc = t & 1;
        const __nv_bfloat16* h1phi = g_H1hi[pp]; const __nv_bfloat16* h1plo = g_H1lo[pp];
        const __nv_bfloat16* h2phi = g_H2hi[pc]; const __nv_bfloat16* h2plo = g_H2lo[pc];

        if (isA) {
            stageA_ws(t, h1phi, h1plo);
            CP_WAIT(0);
            NAMED_BAR(1);
            computeWS(OFF_WA_HI, OFF_WA_LO, OFF_AA_HI, OFF_AA_LO, SA, 9, scrA, 1);
            if (tid == 0) {
                MBAR_ARRIVE_RANK(mbA, 0); MBAR_ARRIVE_RANK(mbA, 1);
                MBAR_ARRIVE_RANK(mbA, 2); MBAR_ARRIVE_RANK(mbA, 3);
            }
            MBAR_WAIT_CLUSTER(mbA, phA); phA ^= 1;
            reduceWS(scrA_u32, biasA, g_H1hi[pc], g_H1lo[pc]);
        } else if (t > 0) {
            stageB_ws(h1phi, h1plo, h2phi, h2plo);
            CP_WAIT(0);
            NAMED_BAR(2);
            computeWS(OFF_WB_HI, OFF_WB_LO, OFF_AB_HI, OFF_AB_LO, SB, 16, scrB, 2);
            if (tid == 128) {
                MBAR_ARRIVE_RANK(mbB, 0); MBAR_ARRIVE_RANK(mbB, 1);
                MBAR_ARRIVE_RANK(mbB, 2); MBAR_ARRIVE_RANK(mbB, 3);
            }
            MBAR_WAIT_CLUSTER(mbB, phB); phB ^= 1;
            reduceWS(scrB_u32, biasB, g_H2hi[pp], g_H2lo[pp]);
        }
        group_bar(grp);
    }
    // epilogue: B(511) — h1(511) in buf1, h2(510) in buf0 -> h2(511) in buf1
    if (!isA) {
        stageB_ws(g_H1hi[1], g_H1lo[1], g_H2hi[0], g_H2lo[0]);
        CP_WAIT(0);
        NAMED_BAR(2);
        computeWS(OFF_WB_HI, OFF_WB_LO, OFF_AB_HI, OFF_AB_LO, SB, 16, scrB, 2);
        if (tid == 128) {
            MBAR_ARRIVE_RANK(mbB, 0); MBAR_ARRIVE_RANK(mbB, 1);
            MBAR_ARRIVE_RANK(mbB, 2); MBAR_ARRIVE_RANK(mbB, 3);
        }
        MBAR_WAIT_CLUSTER(mbB, phB); phB ^= 1;
        reduceWS(scrB_u32, biasB, g_H2hi[1], g_H2lo[1]);
    }
    group_bar(grp);

    // ============================ final FC ============================
    static __shared__ float red[8];
    for (int r = 0; r < 2; ++r) {
        int b = bid * 2 + r;
        float s = 0.f;
        for (int h = tid * 2; h < HID; h += NTH * 2) {
            unsigned uh = __ldcg((const unsigned*)(&g_H2hi[1][(size_t)b * HID + h]));
            unsigned ul = __ldcg((const unsigned*)(&g_H2lo[1][(size_t)b * HID + h]));
            __nv_bfloat162 vh = *(__nv_bfloat162*)&uh;
            __nv_bfloat162 vl = *(__nv_bfloat162*)&ul;
            float v0 = __bfloat162float(__low2bfloat16(vh)) + __bfloat162float(__low2bfloat16(vl));
            float v1 = __bfloat162float(__high2bfloat16(vh)) + __bfloat162float(__high2bfloat16(vl));
            s += v0 * W_fc[h] + v1 * W_fc[h + 1];
        }
        #pragma unroll
        for (int off = 16; off; off >>= 1)
            s += __shfl_down_sync(0xffffffffu, s, off);
        if ((tid & 31) == 0) red[tid >> 5] = s;
        __syncthreads();
        if (tid == 0) {
            float tot = b_fc[0];
            #pragma unroll
            for (int w = 0; w < 8; w++) tot += red[w];
            out[b] = tot;
        }
        __syncthreads();
    }
}

extern "C" void kernel_launch(void* const* d_in, const int* in_sizes, int n_in,
                              void* d_out, int out_size) {
    (void)in_sizes; (void)n_in; (void)out_size;
    const float* x     = (const float*)d_in[0];
    const float* W_ih0 = (const float*)d_in[1];
    const float* W_hh0 = (const float*)d_in[2];
    const float* b_ih0 = (const float*)d_in[3];
    const float* b_hh0 = (const float*)d_in[4];
    const float* W_ih1 = (const float*)d_in[5];
    const float* W_hh1 = (const float*)d_in[6];
    const float* b_ih1 = (const float*)d_in[7];
    const float* b_hh1 = (const float*)d_in[8];
    const float* W_fc  = (const float*)d_in[9];
    const float* b_fc  = (const float*)d_in[10];
    float* out = (float*)d_out;

    cudaFuncSetAttribute(rnn_hmma,
                         cudaFuncAttributeMaxDynamicSharedMemorySize, SMEM_BYTES);
    rnn_hmma<<<GRIDN, NTH, SMEM_BYTES>>>(
        x, W_ih0, W_hh0, b_ih0, b_hh0,
        W_ih1, W_hh1, b_ih1, b_hh1, W_fc, b_fc, out);
}

// round 11
// speedup vs baseline: 1.2934x; 1.2934x over previous
#include <cuda_runtime.h>
#include <cuda_bf16.h>
#include <cstddef>

#define BATCH 256
#define SEQ   512
#define DIN   64
#define HID   512
#define GRIDN 128
#define NTH   256

#define TM 64
#define TN 64
#define KA_PER 144          // 576 / 4
#define KB_PER 256          // 1024 / 4

#define SA 152              // A-phase row stride (bf16 elems)
#define SB 264              // B-phase row stride

#define OFF_WA_HI 0
#define OFF_WA_LO (OFF_WA_HI + 64 * SA)
#define OFF_AA_HI (OFF_WA_LO + 64 * SA)
#define OFF_AA_LO (OFF_AA_HI + 64 * SA)
#define OFF_WB_HI (OFF_AA_LO + 64 * SA)
#define OFF_WB_LO (OFF_WB_HI + 64 * SB)
#define OFF_AB_HI (OFF_WB_LO + 64 * SB)
#define OFF_AB_LO (OFF_AB_HI + 64 * SB)
#define ELEMS_TOT (OFF_AB_LO + 64 * SB)          // 106,496 bf16 = 212,992 B
#define SCR_STRIDE 68                            // fp32; rows 16B-aligned
#define SMEM_BYTES (ELEMS_TOT * 2 + 64 * SCR_STRIDE * 4)   // 230,400 B

typedef unsigned long long ull;

// ---------------- cross-CTA state (static scratch; allocation-free) ----------------
__device__ __nv_bfloat16 g_Xhi[BATCH * SEQ * DIN];
__device__ __nv_bfloat16 g_Xlo[BATCH * SEQ * DIN];
__device__ __nv_bfloat16 g_H1hi[2][BATCH * HID], g_H1lo[2][BATCH * HID];
__device__ __nv_bfloat16 g_H2hi[2][BATCH * HID], g_H2lo[2][BATCH * HID];

struct __align__(128) Line { unsigned v; unsigned pad[31]; };
__device__ Line g_leaf[8];
__device__ Line g_root;
__device__ Line g_gen;
__device__ Line g_gcnt[4];     // per-row-group barrier counters
__device__ Line g_ggen[4];     // per-row-group generations

// full-grid tree barrier (init only)
__device__ __forceinline__ void grid_sync_init(int leaf) {
    __syncthreads();
    if (threadIdx.x == 0) {
        unsigned gen = *(volatile unsigned*)&g_gen.v;
        __threadfence();
        if (atomicAdd(&g_leaf[leaf].v, 1u) == 15u) {
            g_leaf[leaf].v = 0u;
            __threadfence();
            if (atomicAdd(&g_root.v, 1u) == 7u) {
                g_root.v = 0u;
                __threadfence();
                *(volatile unsigned*)&g_gen.v = gen + 1u;
            } else {
                while (*(volatile unsigned*)&g_gen.v == gen) __nanosleep(16);
            }
        } else {
            while (*(volatile unsigned*)&g_gen.v == gen) __nanosleep(16);
        }
        __threadfence();
    }
    __syncthreads();
}

// per-row-group 32-CTA barrier
__device__ __forceinline__ void group_bar(int grp) {
    __syncthreads();
    if (threadIdx.x == 0) {
        unsigned gen = *(volatile unsigned*)&g_ggen[grp].v;
        __threadfence();
        if (atomicAdd(&g_gcnt[grp].v, 1u) == 31u) {
            g_gcnt[grp].v = 0u;
            __threadfence();
            *(volatile unsigned*)&g_ggen[grp].v = gen + 1u;
        } else {
            while (*(volatile unsigned*)&g_ggen[grp].v == gen) __nanosleep(16);
        }
        __threadfence();
    }
    __syncthreads();
}

#define CLUSTER_SYNC() do { \
    asm volatile("barrier.cluster.arrive.aligned;" ::: "memory"); \
    asm volatile("barrier.cluster.wait.aligned;" ::: "memory"); \
} while (0)

__device__ __forceinline__ unsigned mapa_rank(unsigned smaddr, unsigned rank) {
    unsigned r;
    asm("mapa.shared::cluster.u32 %0, %1, %2;" : "=r"(r) : "r"(smaddr), "r"(rank));
    return r;
}
__device__ __forceinline__ float4 ld_dsmem_f4(unsigned addr) {
    float4 v;
    asm volatile("ld.shared::cluster.v4.f32 {%0,%1,%2,%3}, [%4];"
                 : "=f"(v.x), "=f"(v.y), "=f"(v.z), "=f"(v.w) : "r"(addr));
    return v;
}

__device__ __forceinline__ void mma16816(float* c, const unsigned* a, const unsigned* b) {
    asm volatile(
        "mma.sync.aligned.m16n8k16.row.col.f32.bf16.bf16.f32 "
        "{%0,%1,%2,%3}, {%4,%5,%6,%7}, {%8,%9}, {%0,%1,%2,%3};"
        : "+f"(c[0]), "+f"(c[1]), "+f"(c[2]), "+f"(c[3])
        : "r"(a[0]), "r"(a[1]), "r"(a[2]), "r"(a[3]), "r"(b[0]), "r"(b[1]));
}

#define CP16(dst_u32, src_ptr) \
    asm volatile("cp.async.cg.shared.global [%0], [%1], 16;" \
                 :: "r"(dst_u32), "l"(src_ptr))
#define CP_COMMIT() asm volatile("cp.async.commit_group;")
#define CP_WAIT(n)  asm volatile("cp.async.wait_group %0;" :: "n"(n))

__device__ __forceinline__ void split_bf16(float v, __nv_bfloat16& hi, __nv_bfloat16& lo) {
    hi = __float2bfloat16_rn(v);
    lo = __float2bfloat16_rn(v - __bfloat162float(hi));
}

__global__ void __launch_bounds__(NTH, 1) __cluster_dims__(4, 1, 1) rnn_hmma(
    const float* __restrict__ x,
    const float* __restrict__ W_ih0, const float* __restrict__ W_hh0,
    const float* __restrict__ b_ih0, const float* __restrict__ b_hh0,
    const float* __restrict__ W_ih1, const float* __restrict__ W_hh1,
    const float* __restrict__ b_ih1, const float* __restrict__ b_hh1,
    const float* __restrict__ W_fc,  const float* __restrict__ b_fc,
    float* __restrict__ out)
{
    const int tid  = threadIdx.x;
    const int bid  = blockIdx.x;
    const int leaf = bid & 7;
    const int grp  = bid >> 5;       // row group (mt)
    const int ks   = bid & 3;        // cluster rank
    const int tile = bid >> 2;
    const int mt   = tile >> 3;
    const int nt   = tile & 7;
    const int m0   = mt * TM;
    const int n0   = nt * TN;

    extern __shared__ __nv_bfloat16 sm[];
    float* scrA = (float*)(sm + ELEMS_TOT);      // dedicated scratch
    float* scrB = (float*)(sm + OFF_AA_HI);      // aliases AA staging (dead in phase B)
    const unsigned sm_u32   = (unsigned)__cvta_generic_to_shared(sm);
    const unsigned scrA_u32 = sm_u32 + ELEMS_TOT * 2;
    const unsigned scrB_u32 = sm_u32 + OFF_AA_HI * 2;

    // ---------- one-time: split weight slices -> SMEM ----------
    {
        const int kb = ks * KA_PER;
        for (int idx = tid; idx < 64 * KA_PER; idx += NTH) {
            int n = idx / KA_PER, k = idx - n * KA_PER;
            int kg = kb + k;
            float v = (kg < DIN) ? W_ih0[(n0 + n) * DIN + kg]
                                 : W_hh0[(n0 + n) * HID + (kg - DIN)];
            __nv_bfloat16 hi, lo; split_bf16(v, hi, lo);
            sm[OFF_WA_HI + n * SA + k] = hi;
            sm[OFF_WA_LO + n * SA + k] = lo;
        }
        const int kbb = ks * KB_PER;
        for (int idx = tid; idx < 64 * KB_PER; idx += NTH) {
            int n = idx / KB_PER, k = idx - n * KB_PER;
            int kg = kbb + k;
            float v = (kg < HID) ? W_ih1[(n0 + n) * HID + kg]
                                 : W_hh1[(n0 + n) * HID + (kg - HID)];
            __nv_bfloat16 hi, lo; split_bf16(v, hi, lo);
            sm[OFF_WB_HI + n * SB + k] = hi;
            sm[OFF_WB_LO + n * SB + k] = lo;
        }
    }
    // ---------- one-time: pre-split x ----------
    {
        const int total = BATCH * SEQ * DIN;
        for (int i = (bid * NTH + tid) * 4; i < total; i += GRIDN * NTH * 4) {
            float4 v = *(const float4*)(x + i);
            __nv_bfloat16 h0,h1,h2,h3,l0,l1,l2,l3;
            split_bf16(v.x,h0,l0); split_bf16(v.y,h1,l1);
            split_bf16(v.z,h2,l2); split_bf16(v.w,h3,l3);
            *(__nv_bfloat162*)(g_Xhi + i)     = __halves2bfloat162(h0, h1);
            *(__nv_bfloat162*)(g_Xhi + i + 2) = __halves2bfloat162(h2, h3);
            *(__nv_bfloat162*)(g_Xlo + i)     = __halves2bfloat162(l0, l1);
            *(__nv_bfloat162*)(g_Xlo + i + 2) = __halves2bfloat162(l2, l3);
        }
    }
    // ---------- zero t=-1 states (buffer 1) ----------
    {
        const int per = (BATCH * HID) / GRIDN;
        const int base = bid * per;
        __nv_bfloat162 z = __halves2bfloat162(__float2bfloat16(0.f), __float2bfloat16(0.f));
        for (int i = tid * 2; i < per; i += NTH * 2) {
            *(__nv_bfloat162*)(&g_H1hi[1][base + i]) = z;
            *(__nv_bfloat162*)(&g_H1lo[1][base + i]) = z;
            *(__nv_bfloat162*)(&g_H2hi[1][base + i]) = z;
            *(__nv_bfloat162*)(&g_H2lo[1][base + i]) = z;
        }
    }
    grid_sync_init(leaf);

    // ---------- roles ----------
    const int lane = tid & 31;
    const int wid  = tid >> 5;
    const int wm   = wid & 1;
    const int wn   = (wid >> 1) & 1;
    const int wk   = wid >> 2;
    const int q    = lane >> 2;
    const int tg2  = (lane & 3) * 2;

    const int s_k   = lane * 8;
    const int s_row = wid;

    // reduce role: cluster-wide 1024 threads cover 64x64 tile
    const int gtid = ks * NTH + tid;
    const int rr = gtid >> 4;
    const int cc = (gtid & 15) << 2;
    float4 biasA, biasB;
    {
        float4 bi = *(const float4*)(b_ih0 + n0 + cc);
        float4 bh = *(const float4*)(b_hh0 + n0 + cc);
        biasA = make_float4(bi.x+bh.x, bi.y+bh.y, bi.z+bh.z, bi.w+bh.w);
        bi = *(const float4*)(b_ih1 + n0 + cc);
        bh = *(const float4*)(b_hh1 + n0 + cc);
        biasB = make_float4(bi.x+bh.x, bi.y+bh.y, bi.z+bh.z, bi.w+bh.w);
    }
    const unsigned redoff = (unsigned)(rr * SCR_STRIDE + cc) * 4u;

    // ---------- async staging ----------
    auto stageA_async = [&](int t, const __nv_bfloat16* h1phi, const __nv_bfloat16* h1plo) {
        if (s_k < KA_PER) {
            const int kg = ks * KA_PER + s_k;
            #pragma unroll
            for (int it = 0; it < 8; ++it) {
                int row = s_row + it * 8;
                int mgr = m0 + row;
                const __nv_bfloat16 *ph, *pl;
                if (kg < DIN) {
                    size_t off = (size_t)mgr * (SEQ * DIN) + (size_t)t * DIN + kg;
                    ph = g_Xhi + off; pl = g_Xlo + off;
                } else {
                    size_t off = (size_t)mgr * HID + (kg - DIN);
                    ph = h1phi + off; pl = h1plo + off;
                }
                CP16(sm_u32 + (OFF_AA_HI + row * SA + s_k) * 2, ph);
                CP16(sm_u32 + (OFF_AA_LO + row * SA + s_k) * 2, pl);
            }
        }
        CP_COMMIT();
    };
    auto stageB_async = [&](const __nv_bfloat16* h1phi, const __nv_bfloat16* h1plo,
                            const __nv_bfloat16* h2phi, const __nv_bfloat16* h2plo) {
        const int kg = ks * KB_PER + s_k;
        const int koff = (ks < 2) ? kg : kg - HID;
        const __nv_bfloat16* shi = (ks < 2) ? h1phi : h2phi;
        const __nv_bfloat16* slo = (ks < 2) ? h1plo : h2plo;
        #pragma unroll
        for (int it = 0; it < 8; ++it) {
            int row = s_row + it * 8;
            size_t off = (size_t)(m0 + row) * HID + koff;
            CP16(sm_u32 + (OFF_AB_HI + row * SB + s_k) * 2, shi + off);
            CP16(sm_u32 + (OFF_AB_LO + row * SB + s_k) * 2, slo + off);
        }
        CP_COMMIT();
    };

    // ---------- GEMM phase: 3-split HMMA; k-halves merged into scrp ----------
    auto computePhase = [&](int offWhi, int offWlo, int offAhi, int offAlo, int st,
                            int ks0, int ks1, float* __restrict__ scrp) {
        float acc[2][4][4];
        #pragma unroll
        for (int f = 0; f < 2; f++)
            #pragma unroll
            for (int g = 0; g < 4; g++)
                #pragma unroll
                for (int i = 0; i < 4; i++) acc[f][g][i] = 0.f;

        const __nv_bfloat16* Ah = sm + offAhi;
        const __nv_bfloat16* Al = sm + offAlo;
        const __nv_bfloat16* Wh = sm + offWhi;
        const __nv_bfloat16* Wl = sm + offWlo;
        const int r00 = wm * 32 + q;

        for (int kst = ks0; kst < ks1; ++kst) {
            const int kb = kst * 16 + tg2;
            unsigned ah[2][4], al[2][4], bh[4][2], bl[4][2];
            #pragma unroll
            for (int f = 0; f < 2; f++) {
                int r = (r00 + f * 16) * st;
                ah[f][0] = *(const unsigned*)(Ah + r + kb);
                ah[f][1] = *(const unsigned*)(Ah + r + 8 * st + kb);
                ah[f][2] = *(const unsigned*)(Ah + r + kb + 8);
                ah[f][3] = *(const unsigned*)(Ah + r + 8 * st + kb + 8);
                al[f][0] = *(const unsigned*)(Al + r + kb);
                al[f][1] = *(const unsigned*)(Al + r + 8 * st + kb);
                al[f][2] = *(const unsigned*)(Al + r + kb + 8);
                al[f][3] = *(const unsigned*)(Al + r + 8 * st + kb + 8);
            }
            #pragma unroll
            for (int g = 0; g < 4; g++) {
                int nr = (wn * 32 + g * 8 + q) * st;
                bh[g][0] = *(const unsigned*)(Wh + nr + kb);
                bh[g][1] = *(const unsigned*)(Wh + nr + kb + 8);
                bl[g][0] = *(const unsigned*)(Wl + nr + kb);
                bl[g][1] = *(const unsigned*)(Wl + nr + kb + 8);
            }
            #pragma unroll
            for (int f = 0; f < 2; f++)
                #pragma unroll
                for (int g = 0; g < 4; g++) {
                    mma16816(acc[f][g], ah[f], bh[g]);
                    mma16816(acc[f][g], al[f], bh[g]);
                    mma16816(acc[f][g], ah[f], bl[g]);
                }
        }
        if (wk == 1) {
            #pragma unroll
            for (int f = 0; f < 2; f++)
                #pragma unroll
                for (int g = 0; g < 4; g++) {
                    int r = wm * 32 + f * 16 + q;
                    int c = wn * 32 + g * 8 + tg2;
                    *(float2*)(scrp + r * SCR_STRIDE + c) =
                        make_float2(acc[f][g][0], acc[f][g][1]);
                    *(float2*)(scrp + (r + 8) * SCR_STRIDE + c) =
                        make_float2(acc[f][g][2], acc[f][g][3]);
                }
        }
        __syncthreads();
        if (wk == 0) {
            #pragma unroll
            for (int f = 0; f < 2; f++)
                #pragma unroll
                for (int g = 0; g < 4; g++) {
                    int r = wm * 32 + f * 16 + q;
                    int c = wn * 32 + g * 8 + tg2;
                    float2 o0 = *(const float2*)(scrp + r * SCR_STRIDE + c);
                    float2 o1 = *(const float2*)(scrp + (r + 8) * SCR_STRIDE + c);
                    *(float2*)(scrp + r * SCR_STRIDE + c) =
                        make_float2(acc[f][g][0] + o0.x, acc[f][g][1] + o0.y);
                    *(float2*)(scrp + (r + 8) * SCR_STRIDE + c) =
                        make_float2(acc[f][g][2] + o1.x, acc[f][g][3] + o1.y);
                }
        }
    };

    // tanh + split + store helper
    auto finishH = [&](float4 s, __nv_bfloat16* __restrict__ dhi,
                       __nv_bfloat16* __restrict__ dlo) {
        float h0 = tanhf(s.x), h1 = tanhf(s.y), h2 = tanhf(s.z), h3 = tanhf(s.w);
        __nv_bfloat16 hi0,hi1,hi2,hi3, lo0,lo1,lo2,lo3;
        split_bf16(h0,hi0,lo0); split_bf16(h1,hi1,lo1);
        split_bf16(h2,hi2,lo2); split_bf16(h3,hi3,lo3);
        __nv_bfloat162 ph0 = __halves2bfloat162(hi0,hi1), ph1 = __halves2bfloat162(hi2,hi3);
        __nv_bfloat162 pl0 = __halves2bfloat162(lo0,lo1), pl1 = __halves2bfloat162(lo2,lo3);
        uint2 uh, ul;
        uh.x = *(unsigned*)&ph0; uh.y = *(unsigned*)&ph1;
        ul.x = *(unsigned*)&pl0; ul.y = *(unsigned*)&pl1;
        size_t doff = (size_t)(m0 + rr) * HID + n0 + cc;
        __stcg((uint2*)(dhi + doff), uh);
        __stcg((uint2*)(dlo + doff), ul);
    };

    // merged reduce: issue all 8 DSMEM loads (MLP 8), then both tanh+stores
    auto reduceAB = [&](bool doB,
                        __nv_bfloat16* d1hi, __nv_bfloat16* d1lo,
                        __nv_bfloat16* d2hi, __nv_bfloat16* d2lo) {
        const unsigned aA = scrA_u32 + redoff;
        const unsigned aB = scrB_u32 + redoff;
        float4 a0 = ld_dsmem_f4(mapa_rank(aA, 0));
        float4 a1 = ld_dsmem_f4(mapa_rank(aA, 1));
        float4 a2 = ld_dsmem_f4(mapa_rank(aA, 2));
        float4 a3 = ld_dsmem_f4(mapa_rank(aA, 3));
        float4 b0, b1, b2, b3;
        if (doB) {
            b0 = ld_dsmem_f4(mapa_rank(aB, 0));
            b1 = ld_dsmem_f4(mapa_rank(aB, 1));
            b2 = ld_dsmem_f4(mapa_rank(aB, 2));
            b3 = ld_dsmem_f4(mapa_rank(aB, 3));
        }
        float4 s;
        s.x = biasA.x + a0.x + a1.x + a2.x + a3.x;
        s.y = biasA.y + a0.y + a1.y + a2.y + a3.y;
        s.z = biasA.z + a0.z + a1.z + a2.z + a3.z;
        s.w = biasA.w + a0.w + a1.w + a2.w + a3.w;
        finishH(s, d1hi, d1lo);
        if (doB) {
            s.x = biasB.x + b0.x + b1.x + b2.x + b3.x;
            s.y = biasB.y + b0.y + b1.y + b2.y + b3.y;
            s.z = biasB.z + b0.z + b1.z + b2.z + b3.z;
            s.w = biasB.w + b0.w + b1.w + b2.w + b3.w;
            finishH(s, d2hi, d2lo);
        }
    };

    const int ksA0 = wk ? 5 : 0, ksA1 = wk ? 9 : 5;
    const int ksB0 = wk ? 8 : 0, ksB1 = wk ? 16 : 8;

    // ============================ main loop ============================
    // step t: A(t) + B(t-1) compute back-to-back; ONE cluster sync; merged reduce;
    // ONE 32-CTA row-group barrier.
    for (int t = 0; t < SEQ; ++t) {
        const int pp = (t + 1) & 1, pc = t & 1;
        const __nv_bfloat16* h1phi = g_H1hi[pp]; const __nv_bfloat16* h1plo = g_H1lo[pp];
        const __nv_bfloat16* h2phi = g_H2hi[pc]; const __nv_bfloat16* h2plo = g_H2lo[pc];

        stageA_async(t, h1phi, h1plo);
        if (t > 0) {
            stageB_async(h1phi, h1plo, h2phi, h2plo);
            CP_WAIT(1);
        } else {
            CP_WAIT(0);
        }
        __syncthreads();
        computePhase(OFF_WA_HI, OFF_WA_LO, OFF_AA_HI, OFF_AA_LO, SA, ksA0, ksA1, scrA);
        if (t > 0) {
            CP_WAIT(0);
            __syncthreads();                // AB staged visible; scrA merge done
            computePhase(OFF_WB_HI, OFF_WB_LO, OFF_AB_HI, OFF_AB_LO, SB, ksB0, ksB1, scrB);
        }
        CLUSTER_SYNC();                     // scrA + scrB visible cluster-wide
        reduceAB(t > 0, g_H1hi[pc], g_H1lo[pc], g_H2hi[pp], g_H2lo[pp]);
        group_bar(grp);                     // publish h1(t), h2(t-1) within row group
    }
    // epilogue: B(511): h1(511) in buf1, h2(510) in buf0 -> h2(511) in buf1
    stageB_async(g_H1hi[1], g_H1lo[1], g_H2hi[0], g_H2lo[0]);
    CP_WAIT(0);
    __syncthreads();
    computePhase(OFF_WB_HI, OFF_WB_LO, OFF_AB_HI, OFF_AB_LO, SB, ksB0, ksB1, scrB);
    CLUSTER_SYNC();
    {
        const unsigned aB = scrB_u32 + redoff;
        float4 b0 = ld_dsmem_f4(mapa_rank(aB, 0));
        float4 b1 = ld_dsmem_f4(mapa_rank(aB, 1));
        float4 b2 = ld_dsmem_f4(mapa_rank(aB, 2));
        float4 b3 = ld_dsmem_f4(mapa_rank(aB, 3));
        float4 s;
        s.x = biasB.x + b0.x + b1.x + b2.x + b3.x;
        s.y = biasB.y + b0.y + b1.y + b2.y + b3.y;
        s.z = biasB.z + b0.z + b1.z + b2.z + b3.z;
        s.w = biasB.w + b0.w + b1.w + b2.w + b3.w;
        finishH(s, g_H2hi[1], g_H2lo[1]);
    }
    group_bar(grp);

    // ============================ final FC ============================
    static __shared__ float red[8];
    for (int r = 0; r < 2; ++r) {
        int b = bid * 2 + r;
        float s = 0.f;
        for (int h = tid * 2; h < HID; h += NTH * 2) {
            unsigned uh = __ldcg((const unsigned*)(&g_H2hi[1][(size_t)b * HID + h]));
            unsigned ul = __ldcg((const unsigned*)(&g_H2lo[1][(size_t)b * HID + h]));
            __nv_bfloat162 vh = *(__nv_bfloat162*)&uh;
            __nv_bfloat162 vl = *(__nv_bfloat162*)&ul;
            float v0 = __bfloat162float(__low2bfloat16(vh)) + __bfloat162float(__low2bfloat16(vl));
            float v1 = __bfloat162float(__high2bfloat16(vh)) + __bfloat162float(__high2bfloat16(vl));
            s += v0 * W_fc[h] + v1 * W_fc[h + 1];
        }
        #pragma unroll
        for (int off = 16; off; off >>= 1)
            s += __shfl_down_sync(0xffffffffu, s, off);
        if ((tid & 31) == 0) red[tid >> 5] = s;
        __syncthreads();
        if (tid == 0) {
            float tot = b_fc[0];
            #pragma unroll
            for (int w = 0; w < 8; w++) tot += red[w];
            out[b] = tot;
        }
        __syncthreads();
    }
}

extern "C" void kernel_launch(void* const* d_in, const int* in_sizes, int n_in,
                              void* d_out, int out_size) {
    (void)in_sizes; (void)n_in; (void)out_size;
    const float* x     = (const float*)d_in[0];
    const float* W_ih0 = (const float*)d_in[1];
    const float* W_hh0 = (const float*)d_in[2];
    const float* b_ih0 = (const float*)d_in[3];
    const float* b_hh0 = (const float*)d_in[4];
    const float* W_ih1 = (const float*)d_in[5];
    const float* W_hh1 = (const float*)d_in[6];
    const float* b_ih1 = (const float*)d_in[7];
    const float* b_hh1 = (const float*)d_in[8];
    const float* W_fc  = (const float*)d_in[9];
    const float* b_fc  = (const float*)d_in[10];
    float* out = (float*)d_out;

    cudaFuncSetAttribute(rnn_hmma,
                         cudaFuncAttributeMaxDynamicSharedMemorySize, SMEM_BYTES);
    rnn_hmma<<<GRIDN, NTH, SMEM_BYTES>>>(
        x, W_ih0, W_hh0, b_ih0, b_hh0,
        W_ih1, W_hh1, b_ih1, b_hh1, W_fc, b_fc, out);
}

// round 12
// speedup vs baseline: 1.3446x; 1.0396x over previous
#include <cuda_runtime.h>
#include <cuda_bf16.h>
#include <cstddef>

#define BATCH 256
#define SEQ   512
#define DIN   64
#define HID   512
#define GRIDN 128
#define NTH   256

#define TM 64
#define TN 64
#define KA_PER 144          // 576 / 4
#define KB_PER 256          // 1024 / 4

#define SA 152              // A-phase row stride (bf16 elems)
#define SB 264              // B-phase row stride

#define OFF_WA_HI 0
#define OFF_WA_LO (OFF_WA_HI + 64 * SA)
#define OFF_AA_HI (OFF_WA_LO + 64 * SA)
#define OFF_AA_LO (OFF_AA_HI + 64 * SA)
#define OFF_WB_HI (OFF_AA_LO + 64 * SA)
#define OFF_WB_LO (OFF_WB_HI + 64 * SB)
#define OFF_AB_HI (OFF_WB_LO + 64 * SB)
#define OFF_AB_LO (OFF_AB_HI + 64 * SB)
#define ELEMS_TOT (OFF_AB_LO + 64 * SB)          // 106,496 bf16 = 212,992 B
#define SCR_STRIDE 68                            // fp32; rows 16B-aligned
#define SMEM_BYTES (ELEMS_TOT * 2 + 64 * SCR_STRIDE * 4)   // 230,400 B

typedef unsigned long long ull;

// ---------------- cross-CTA state (static scratch; allocation-free) ----------------
__device__ __nv_bfloat16 g_Xhi[BATCH * SEQ * DIN];
__device__ __nv_bfloat16 g_Xlo[BATCH * SEQ * DIN];
__device__ __nv_bfloat16 g_H1hi[2][BATCH * HID], g_H1lo[2][BATCH * HID];
__device__ __nv_bfloat16 g_H2hi[2][BATCH * HID], g_H2lo[2][BATCH * HID];

struct __align__(128) Line { unsigned v; unsigned pad[31]; };
__device__ Line g_leaf[8];
__device__ Line g_root;
__device__ Line g_gen;
__device__ Line g_gcnt[4];
__device__ Line g_ggen[4];

__device__ __forceinline__ void grid_sync_init(int leaf) {
    __syncthreads();
    if (threadIdx.x == 0) {
        unsigned gen = *(volatile unsigned*)&g_gen.v;
        __threadfence();
        if (atomicAdd(&g_leaf[leaf].v, 1u) == 15u) {
            g_leaf[leaf].v = 0u;
            __threadfence();
            if (atomicAdd(&g_root.v, 1u) == 7u) {
                g_root.v = 0u;
                __threadfence();
                *(volatile unsigned*)&g_gen.v = gen + 1u;
            } else {
                while (*(volatile unsigned*)&g_gen.v == gen) __nanosleep(16);
            }
        } else {
            while (*(volatile unsigned*)&g_gen.v == gen) __nanosleep(16);
        }
        __threadfence();
    }
    __syncthreads();
}

__device__ __forceinline__ void group_bar(int grp) {
    __syncthreads();
    if (threadIdx.x == 0) {
        unsigned gen = *(volatile unsigned*)&g_ggen[grp].v;
        __threadfence();
        if (atomicAdd(&g_gcnt[grp].v, 1u) == 31u) {
            g_gcnt[grp].v = 0u;
            __threadfence();
            *(volatile unsigned*)&g_ggen[grp].v = gen + 1u;
        } else {
            while (*(volatile unsigned*)&g_ggen[grp].v == gen) __nanosleep(16);
        }
        __threadfence();
    }
    __syncthreads();
}

#define CLUSTER_SYNC() do { \
    asm volatile("barrier.cluster.arrive.aligned;" ::: "memory"); \
    asm volatile("barrier.cluster.wait.aligned;" ::: "memory"); \
} while (0)

__device__ __forceinline__ unsigned mapa_rank(unsigned smaddr, unsigned rank) {
    unsigned r;
    asm("mapa.shared::cluster.u32 %0, %1, %2;" : "=r"(r) : "r"(smaddr), "r"(rank));
    return r;
}
__device__ __forceinline__ float4 ld_dsmem_f4(unsigned addr) {
    float4 v;
    asm volatile("ld.shared::cluster.v4.f32 {%0,%1,%2,%3}, [%4];"
                 : "=f"(v.x), "=f"(v.y), "=f"(v.z), "=f"(v.w) : "r"(addr));
    return v;
}

__device__ __forceinline__ void mma16816(float* c, const unsigned* a, const unsigned* b) {
    asm volatile(
        "mma.sync.aligned.m16n8k16.row.col.f32.bf16.bf16.f32 "
        "{%0,%1,%2,%3}, {%4,%5,%6,%7}, {%8,%9}, {%0,%1,%2,%3};"
        : "+f"(c[0]), "+f"(c[1]), "+f"(c[2]), "+f"(c[3])
        : "r"(a[0]), "r"(a[1]), "r"(a[2]), "r"(a[3]), "r"(b[0]), "r"(b[1]));
}

__device__ __forceinline__ void ldsm_x4(unsigned& r0, unsigned& r1,
                                        unsigned& r2, unsigned& r3, unsigned addr) {
    asm volatile("ldmatrix.sync.aligned.m8n8.x4.shared.b16 {%0,%1,%2,%3}, [%4];"
                 : "=r"(r0), "=r"(r1), "=r"(r2), "=r"(r3) : "r"(addr));
}

#define CP16(dst_u32, src_ptr) \
    asm volatile("cp.async.cg.shared.global [%0], [%1], 16;" \
                 :: "r"(dst_u32), "l"(src_ptr))
#define CP_COMMIT() asm volatile("cp.async.commit_group;")
#define CP_WAIT(n)  asm volatile("cp.async.wait_group %0;" :: "n"(n))

__device__ __forceinline__ void split_bf16(float v, __nv_bfloat16& hi, __nv_bfloat16& lo) {
    hi = __float2bfloat16_rn(v);
    lo = __float2bfloat16_rn(v - __bfloat162float(hi));
}

__global__ void __launch_bounds__(NTH, 1) __cluster_dims__(4, 1, 1) rnn_hmma(
    const float* __restrict__ x,
    const float* __restrict__ W_ih0, const float* __restrict__ W_hh0,
    const float* __restrict__ b_ih0, const float* __restrict__ b_hh0,
    const float* __restrict__ W_ih1, const float* __restrict__ W_hh1,
    const float* __restrict__ b_ih1, const float* __restrict__ b_hh1,
    const float* __restrict__ W_fc,  const float* __restrict__ b_fc,
    float* __restrict__ out)
{
    const int tid  = threadIdx.x;
    const int bid  = blockIdx.x;
    const int leaf = bid & 7;
    const int grp  = bid >> 5;
    const int ks   = bid & 3;
    const int tile = bid >> 2;
    const int mt   = tile >> 3;
    const int nt   = tile & 7;
    const int m0   = mt * TM;
    const int n0   = nt * TN;

    extern __shared__ __nv_bfloat16 sm[];
    float* scrA = (float*)(sm + ELEMS_TOT);
    float* scrB = (float*)(sm + OFF_AA_HI);      // aliases AA staging (dead in phase B)
    const unsigned sm_u32   = (unsigned)__cvta_generic_to_shared(sm);
    const unsigned scrA_u32 = sm_u32 + ELEMS_TOT * 2;
    const unsigned scrB_u32 = sm_u32 + OFF_AA_HI * 2;

    // ---------- one-time: split weight slices -> SMEM ----------
    {
        const int kb = ks * KA_PER;
        for (int idx = tid; idx < 64 * KA_PER; idx += NTH) {
            int n = idx / KA_PER, k = idx - n * KA_PER;
            int kg = kb + k;
            float v = (kg < DIN) ? W_ih0[(n0 + n) * DIN + kg]
                                 : W_hh0[(n0 + n) * HID + (kg - DIN)];
            __nv_bfloat16 hi, lo; split_bf16(v, hi, lo);
            sm[OFF_WA_HI + n * SA + k] = hi;
            sm[OFF_WA_LO + n * SA + k] = lo;
        }
        const int kbb = ks * KB_PER;
        for (int idx = tid; idx < 64 * KB_PER; idx += NTH) {
            int n = idx / KB_PER, k = idx - n * KB_PER;
            int kg = kbb + k;
            float v = (kg < HID) ? W_ih1[(n0 + n) * HID + kg]
                                 : W_hh1[(n0 + n) * HID + (kg - HID)];
            __nv_bfloat16 hi, lo; split_bf16(v, hi, lo);
            sm[OFF_WB_HI + n * SB + k] = hi;
            sm[OFF_WB_LO + n * SB + k] = lo;
        }
    }
    // ---------- one-time: pre-split x ----------
    {
        const int total = BATCH * SEQ * DIN;
        for (int i = (bid * NTH + tid) * 4; i < total; i += GRIDN * NTH * 4) {
            float4 v = *(const float4*)(x + i);
            __nv_bfloat16 h0,h1,h2,h3,l0,l1,l2,l3;
            split_bf16(v.x,h0,l0); split_bf16(v.y,h1,l1);
            split_bf16(v.z,h2,l2); split_bf16(v.w,h3,l3);
            *(__nv_bfloat162*)(g_Xhi + i)     = __halves2bfloat162(h0, h1);
            *(__nv_bfloat162*)(g_Xhi + i + 2) = __halves2bfloat162(h2, h3);
            *(__nv_bfloat162*)(g_Xlo + i)     = __halves2bfloat162(l0, l1);
            *(__nv_bfloat162*)(g_Xlo + i + 2) = __halves2bfloat162(l2, l3);
        }
    }
    // ---------- zero t=-1 states (buffer 1) ----------
    {
        const int per = (BATCH * HID) / GRIDN;
        const int base = bid * per;
        __nv_bfloat162 z = __halves2bfloat162(__float2bfloat16(0.f), __float2bfloat16(0.f));
        for (int i = tid * 2; i < per; i += NTH * 2) {
            *(__nv_bfloat162*)(&g_H1hi[1][base + i]) = z;
            *(__nv_bfloat162*)(&g_H1lo[1][base + i]) = z;
            *(__nv_bfloat162*)(&g_H2hi[1][base + i]) = z;
            *(__nv_bfloat162*)(&g_H2lo[1][base + i]) = z;
        }
    }
    grid_sync_init(leaf);

    // ---------- roles ----------
    const int lane = tid & 31;
    const int wid  = tid >> 5;
    const int wm   = wid & 1;
    const int wn   = (wid >> 1) & 1;
    const int wk   = wid >> 2;
    const int q    = lane >> 2;
    const int tg2  = (lane & 3) * 2;

    const int s_k   = lane * 8;
    const int s_row = wid;

    // ldmatrix lane offsets
    const int a_row = lane & 15;               // A: row within 16-row block
    const int a_col = (lane & 16) >> 1;        // A: 0 or 8 (k-block)
    const int b_row = ((lane & 16) >> 1) + (lane & 7);  // B: row within 16-n block
    const int b_col = lane & 8;                // B: 0 or 8 (k-block)

    // reduce role
    const int gtid = ks * NTH + tid;
    const int rr = gtid >> 4;
    const int cc = (gtid & 15) << 2;
    float4 biasA, biasB;
    {
        float4 bi = *(const float4*)(b_ih0 + n0 + cc);
        float4 bh = *(const float4*)(b_hh0 + n0 + cc);
        biasA = make_float4(bi.x+bh.x, bi.y+bh.y, bi.z+bh.z, bi.w+bh.w);
        bi = *(const float4*)(b_ih1 + n0 + cc);
        bh = *(const float4*)(b_hh1 + n0 + cc);
        biasB = make_float4(bi.x+bh.x, bi.y+bh.y, bi.z+bh.z, bi.w+bh.w);
    }
    const unsigned redoff = (unsigned)(rr * SCR_STRIDE + cc) * 4u;

    // ---------- async staging ----------
    auto stageA_async = [&](int t, const __nv_bfloat16* h1phi, const __nv_bfloat16* h1plo) {
        if (s_k < KA_PER) {
            const int kg = ks * KA_PER + s_k;
            #pragma unroll
            for (int it = 0; it < 8; ++it) {
                int row = s_row + it * 8;
                int mgr = m0 + row;
                const __nv_bfloat16 *ph, *pl;
                if (kg < DIN) {
                    size_t off = (size_t)mgr * (SEQ * DIN) + (size_t)t * DIN + kg;
                    ph = g_Xhi + off; pl = g_Xlo + off;
                } else {
                    size_t off = (size_t)mgr * HID + (kg - DIN);
                    ph = h1phi + off; pl = h1plo + off;
                }
                CP16(sm_u32 + (OFF_AA_HI + row * SA + s_k) * 2, ph);
                CP16(sm_u32 + (OFF_AA_LO + row * SA + s_k) * 2, pl);
            }
        }
        CP_COMMIT();
    };
    auto stageB_async = [&](const __nv_bfloat16* h1phi, const __nv_bfloat16* h1plo,
                            const __nv_bfloat16* h2phi, const __nv_bfloat16* h2plo) {
        const int kg = ks * KB_PER + s_k;
        const int koff = (ks < 2) ? kg : kg - HID;
        const __nv_bfloat16* shi = (ks < 2) ? h1phi : h2phi;
        const __nv_bfloat16* slo = (ks < 2) ? h1plo : h2plo;
        #pragma unroll
        for (int it = 0; it < 8; ++it) {
            int row = s_row + it * 8;
            size_t off = (size_t)(m0 + row) * HID + koff;
            CP16(sm_u32 + (OFF_AB_HI + row * SB + s_k) * 2, shi + off);
            CP16(sm_u32 + (OFF_AB_LO + row * SB + s_k) * 2, slo + off);
        }
        CP_COMMIT();
    };

    // ---------- GEMM phase: 3-split HMMA via ldmatrix; k-halves merged into scrp ----------
    auto computePhase = [&](int offWhi, int offWlo, int offAhi, int offAlo, int st,
                            int ks0, int ks1, float* __restrict__ scrp) {
        float acc[2][4][4];
        #pragma unroll
        for (int f = 0; f < 2; f++)
            #pragma unroll
            for (int g = 0; g < 4; g++)
                #pragma unroll
                for (int i = 0; i < 4; i++) acc[f][g][i] = 0.f;

        // ldmatrix base addresses (bytes, shared space), before k advance
        unsigned aHiB[2], aLoB[2], bHiB[2], bLoB[2];
        #pragma unroll
        for (int f = 0; f < 2; f++) {
            unsigned roff = (unsigned)((wm * 32 + f * 16 + a_row) * st + a_col);
            aHiB[f] = sm_u32 + (offAhi + roff) * 2;
            aLoB[f] = sm_u32 + (offAlo + roff) * 2;
        }
        #pragma unroll
        for (int p = 0; p < 2; p++) {
            unsigned roff = (unsigned)((wn * 32 + p * 16 + b_row) * st + b_col);
            bHiB[p] = sm_u32 + (offWhi + roff) * 2;
            bLoB[p] = sm_u32 + (offWlo + roff) * 2;
        }

        for (int kst = ks0; kst < ks1; ++kst) {
            const unsigned kadv = (unsigned)(kst * 16) * 2;   // bytes
            unsigned ah[2][4], al[2][4], bh[4][2], bl[4][2];
            #pragma unroll
            for (int f = 0; f < 2; f++) {
                ldsm_x4(ah[f][0], ah[f][1], ah[f][2], ah[f][3], aHiB[f] + kadv);
                ldsm_x4(al[f][0], al[f][1], al[f][2], al[f][3], aLoB[f] + kadv);
            }
            #pragma unroll
            for (int p = 0; p < 2; p++) {
                ldsm_x4(bh[2*p][0], bh[2*p][1], bh[2*p+1][0], bh[2*p+1][1], bHiB[p] + kadv);
                ldsm_x4(bl[2*p][0], bl[2*p][1], bl[2*p+1][0], bl[2*p+1][1], bLoB[p] + kadv);
            }
            #pragma unroll
            for (int f = 0; f < 2; f++)
                #pragma unroll
                for (int g = 0; g < 4; g++) {
                    mma16816(acc[f][g], ah[f], bh[g]);
                    mma16816(acc[f][g], al[f], bh[g]);
                    mma16816(acc[f][g], ah[f], bl[g]);
                }
        }
        if (wk == 1) {
            #pragma unroll
            for (int f = 0; f < 2; f++)
                #pragma unroll
                for (int g = 0; g < 4; g++) {
                    int r = wm * 32 + f * 16 + q;
                    int c = wn * 32 + g * 8 + tg2;
                    *(float2*)(scrp + r * SCR_STRIDE + c) =
                        make_float2(acc[f][g][0], acc[f][g][1]);
                    *(float2*)(scrp + (r + 8) * SCR_STRIDE + c) =
                        make_float2(acc[f][g][2], acc[f][g][3]);
                }
        }
        __syncthreads();
        if (wk == 0) {
            #pragma unroll
            for (int f = 0; f < 2; f++)
                #pragma unroll
                for (int g = 0; g < 4; g++) {
                    int r = wm * 32 + f * 16 + q;
                    int c = wn * 32 + g * 8 + tg2;
                    float2 o0 = *(const float2*)(scrp + r * SCR_STRIDE + c);
                    float2 o1 = *(const float2*)(scrp + (r + 8) * SCR_STRIDE + c);
                    *(float2*)(scrp + r * SCR_STRIDE + c) =
                        make_float2(acc[f][g][0] + o0.x, acc[f][g][1] + o0.y);
                    *(float2*)(scrp + (r + 8) * SCR_STRIDE + c) =
                        make_float2(acc[f][g][2] + o1.x, acc[f][g][3] + o1.y);
                }
        }
    };

    // tanh + split + store helper
    auto finishH = [&](float4 s, __nv_bfloat16* __restrict__ dhi,
                       __nv_bfloat16* __restrict__ dlo) {
        float h0 = tanhf(s.x), h1 = tanhf(s.y), h2 = tanhf(s.z), h3 = tanhf(s.w);
        __nv_bfloat16 hi0,hi1,hi2,hi3, lo0,lo1,lo2,lo3;
        split_bf16(h0,hi0,lo0); split_bf16(h1,hi1,lo1);
        split_bf16(h2,hi2,lo2); split_bf16(h3,hi3,lo3);
        __nv_bfloat162 ph0 = __halves2bfloat162(hi0,hi1), ph1 = __halves2bfloat162(hi2,hi3);
        __nv_bfloat162 pl0 = __halves2bfloat162(lo0,lo1), pl1 = __halves2bfloat162(lo2,lo3);
        uint2 uh, ul;
        uh.x = *(unsigned*)&ph0; uh.y = *(unsigned*)&ph1;
        ul.x = *(unsigned*)&pl0; ul.y = *(unsigned*)&pl1;
        size_t doff = (size_t)(m0 + rr) * HID + n0 + cc;
        __stcg((uint2*)(dhi + doff), uh);
        __stcg((uint2*)(dlo + doff), ul);
    };

    // merged reduce: all 8 DSMEM loads first (MLP 8), then tanh + stores
    auto reduceAB = [&](bool doB,
                        __nv_bfloat16* d1hi, __nv_bfloat16* d1lo,
                        __nv_bfloat16* d2hi, __nv_bfloat16* d2lo) {
        const unsigned aA = scrA_u32 + redoff;
        const unsigned aB = scrB_u32 + redoff;
        float4 a0 = ld_dsmem_f4(mapa_rank(aA, 0));
        float4 a1 = ld_dsmem_f4(mapa_rank(aA, 1));
        float4 a2 = ld_dsmem_f4(mapa_rank(aA, 2));
        float4 a3 = ld_dsmem_f4(mapa_rank(aA, 3));
        float4 b0, b1, b2, b3;
        if (doB) {
            b0 = ld_dsmem_f4(mapa_rank(aB, 0));
            b1 = ld_dsmem_f4(mapa_rank(aB, 1));
            b2 = ld_dsmem_f4(mapa_rank(aB, 2));
            b3 = ld_dsmem_f4(mapa_rank(aB, 3));
        }
        float4 s;
        s.x = biasA.x + a0.x + a1.x + a2.x + a3.x;
        s.y = biasA.y + a0.y + a1.y + a2.y + a3.y;
        s.z = biasA.z + a0.z + a1.z + a2.z + a3.z;
        s.w = biasA.w + a0.w + a1.w + a2.w + a3.w;
        finishH(s, d1hi, d1lo);
        if (doB) {
            s.x = biasB.x + b0.x + b1.x + b2.x + b3.x;
            s.y = biasB.y + b0.y + b1.y + b2.y + b3.y;
            s.z = biasB.z + b0.z + b1.z + b2.z + b3.z;
            s.w = biasB.w + b0.w + b1.w + b2.w + b3.w;
            finishH(s, d2hi, d2lo);
        }
    };

    const int ksA0 = wk ? 5 : 0, ksA1 = wk ? 9 : 5;
    const int ksB0 = wk ? 8 : 0, ksB1 = wk ? 16 : 8;

    // ============================ main loop ============================
    for (int t = 0; t < SEQ; ++t) {
        const int pp = (t + 1) & 1, pc = t & 1;
        const __nv_bfloat16* h1phi = g_H1hi[pp]; const __nv_bfloat16* h1plo = g_H1lo[pp];
        const __nv_bfloat16* h2phi = g_H2hi[pc]; const __nv_bfloat16* h2plo = g_H2lo[pc];

        stageA_async(t, h1phi, h1plo);
        if (t > 0) {
            stageB_async(h1phi, h1plo, h2phi, h2plo);
            CP_WAIT(1);
        } else {
            CP_WAIT(0);
        }
        __syncthreads();
        computePhase(OFF_WA_HI, OFF_WA_LO, OFF_AA_HI, OFF_AA_LO, SA, ksA0, ksA1, scrA);
        if (t > 0) {
            CP_WAIT(0);
            __syncthreads();
            computePhase(OFF_WB_HI, OFF_WB_LO, OFF_AB_HI, OFF_AB_LO, SB, ksB0, ksB1, scrB);
        }
        CLUSTER_SYNC();
        reduceAB(t > 0, g_H1hi[pc], g_H1lo[pc], g_H2hi[pp], g_H2lo[pp]);
        group_bar(grp);
    }
    // epilogue: B(511): h1(511) in buf1, h2(510) in buf0 -> h2(511) in buf1
    stageB_async(g_H1hi[1], g_H1lo[1], g_H2hi[0], g_H2lo[0]);
    CP_WAIT(0);
    __syncthreads();
    computePhase(OFF_WB_HI, OFF_WB_LO, OFF_AB_HI, OFF_AB_LO, SB, ksB0, ksB1, scrB);
    CLUSTER_SYNC();
    {
        const unsigned aB = scrB_u32 + redoff;
        float4 b0 = ld_dsmem_f4(mapa_rank(aB, 0));
        float4 b1 = ld_dsmem_f4(mapa_rank(aB, 1));
        float4 b2 = ld_dsmem_f4(mapa_rank(aB, 2));
        float4 b3 = ld_dsmem_f4(mapa_rank(aB, 3));
        float4 s;
        s.x = biasB.x + b0.x + b1.x + b2.x + b3.x;
        s.y = biasB.y + b0.y + b1.y + b2.y + b3.y;
        s.z = biasB.z + b0.z + b1.z + b2.z + b3.z;
        s.w = biasB.w + b0.w + b1.w + b2.w + b3.w;
        finishH(s, g_H2hi[1], g_H2lo[1]);
    }
    group_bar(grp);

    // ============================ final FC ============================
    static __shared__ float red[8];
    for (int r = 0; r < 2; ++r) {
        int b = bid * 2 + r;
        float s = 0.f;
        for (int h = tid * 2; h < HID; h += NTH * 2) {
            unsigned uh = __ldcg((const unsigned*)(&g_H2hi[1][(size_t)b * HID + h]));
            unsigned ul = __ldcg((const unsigned*)(&g_H2lo[1][(size_t)b * HID + h]));
            __nv_bfloat162 vh = *(__nv_bfloat162*)&uh;
            __nv_bfloat162 vl = *(__nv_bfloat162*)&ul;
            float v0 = __bfloat162float(__low2bfloat16(vh)) + __bfloat162float(__low2bfloat16(vl));
            float v1 = __bfloat162float(__high2bfloat16(vh)) + __bfloat162float(__high2bfloat16(vl));
            s += v0 * W_fc[h] + v1 * W_fc[h + 1];
        }
        #pragma unroll
        for (int off = 16; off; off >>= 1)
            s += __shfl_down_sync(0xffffffffu, s, off);
        if ((tid & 31) == 0) red[tid >> 5] = s;
        __syncthreads();
        if (tid == 0) {
            float tot = b_fc[0];
            #pragma unroll
            for (int w = 0; w < 8; w++) tot += red[w];
            out[b] = tot;
        }
        __syncthreads();
    }
}

extern "C" void kernel_launch(void* const* d_in, const int* in_sizes, int n_in,
                              void* d_out, int out_size) {
    (void)in_sizes; (void)n_in; (void)out_size;
    const float* x     = (const float*)d_in[0];
    const float* W_ih0 = (const float*)d_in[1];
    const float* W_hh0 = (const float*)d_in[2];
    const float* b_ih0 = (const float*)d_in[3];
    const float* b_hh0 = (const float*)d_in[4];
    const float* W_ih1 = (const float*)d_in[5];
    const float* W_hh1 = (const float*)d_in[6];
    const float* b_ih1 = (const float*)d_in[7];
    const float* b_hh1 = (const float*)d_in[8];
    const float* W_fc  = (const float*)d_in[9];
    const float* b_fc  = (const float*)d_in[10];
    float* out = (float*)d_out;

    cudaFuncSetAttribute(rnn_hmma,
                         cudaFuncAttributeMaxDynamicSharedMemorySize, SMEM_BYTES);
    rnn_hmma<<<GRIDN, NTH, SMEM_BYTES>>>(
        x, W_ih0, W_hh0, b_ih0, b_hh0,
        W_ih1, W_hh1, b_ih1, b_hh1, W_fc, b_fc, out);
}

// round 13
// speedup vs baseline: 1.4210x; 1.0568x over previous
#include <cuda_runtime.h>
#include <cuda_bf16.h>
#include <cstddef>

#define BATCH 256
#define SEQ   512
#define DIN   64
#define HID   512
#define GRIDN 128
#define NTH   256

#define TM 64
#define TN 64
#define KA_PER 144          // 576 / 4
#define KB_PER 256          // 1024 / 4

#define SA 152              // A-phase row stride (bf16 elems)
#define SB 264              // B-phase row stride

#define OFF_WA_HI 0
#define OFF_WA_LO (OFF_WA_HI + 64 * SA)
#define OFF_AA_HI (OFF_WA_LO + 64 * SA)
#define OFF_AA_LO (OFF_AA_HI + 64 * SA)
#define OFF_WB_HI (OFF_AA_LO + 64 * SA)
#define OFF_WB_LO (OFF_WB_HI + 64 * SB)
#define OFF_AB_HI (OFF_WB_LO + 64 * SB)
#define OFF_AB_LO (OFF_AB_HI + 64 * SB)
#define ELEMS_TOT (OFF_AB_LO + 64 * SB)          // 106,496 bf16 = 212,992 B
#define SCR_STRIDE 68                            // fp32; rows 16B-aligned
#define SMEM_BYTES (ELEMS_TOT * 2 + 64 * SCR_STRIDE * 4)   // 230,400 B

typedef unsigned long long ull;

// ---------------- cross-CTA state (static scratch; allocation-free) ----------------
__device__ __nv_bfloat16 g_Xhi[BATCH * SEQ * DIN];
__device__ __nv_bfloat16 g_Xlo[BATCH * SEQ * DIN];
__device__ __nv_bfloat16 g_H1hi[2][BATCH * HID], g_H1lo[2][BATCH * HID];
__device__ __nv_bfloat16 g_H2hi[2][BATCH * HID], g_H2lo[2][BATCH * HID];

struct __align__(128) Line { unsigned v; unsigned pad[31]; };
__device__ Line g_leaf[8];
__device__ Line g_root;
__device__ Line g_gen;
__device__ Line g_flag[GRIDN];   // per-CTA step flags (zero-init)

// full-grid tree barrier (init only)
__device__ __forceinline__ void grid_sync_init(int leaf) {
    __syncthreads();
    if (threadIdx.x == 0) {
        unsigned gen = *(volatile unsigned*)&g_gen.v;
        __threadfence();
        if (atomicAdd(&g_leaf[leaf].v, 1u) == 15u) {
            g_leaf[leaf].v = 0u;
            __threadfence();
            if (atomicAdd(&g_root.v, 1u) == 7u) {
                g_root.v = 0u;
                __threadfence();
                *(volatile unsigned*)&g_gen.v = gen + 1u;
            } else {
                while (*(volatile unsigned*)&g_gen.v == gen) __nanosleep(16);
            }
        } else {
            while (*(volatile unsigned*)&g_gen.v == gen) __nanosleep(16);
        }
        __threadfence();
    }
    __syncthreads();
}

#define CLUSTER_SYNC() do { \
    asm volatile("barrier.cluster.arrive.aligned;" ::: "memory"); \
    asm volatile("barrier.cluster.wait.aligned;" ::: "memory"); \
} while (0)

__device__ __forceinline__ unsigned mapa_rank(unsigned smaddr, unsigned rank) {
    unsigned r;
    asm("mapa.shared::cluster.u32 %0, %1, %2;" : "=r"(r) : "r"(smaddr), "r"(rank));
    return r;
}
__device__ __forceinline__ float4 ld_dsmem_f4(unsigned addr) {
    float4 v;
    asm volatile("ld.shared::cluster.v4.f32 {%0,%1,%2,%3}, [%4];"
                 : "=f"(v.x), "=f"(v.y), "=f"(v.z), "=f"(v.w) : "r"(addr));
    return v;
}

__device__ __forceinline__ void mma16816(float* c, const unsigned* a, const unsigned* b) {
    asm volatile(
        "mma.sync.aligned.m16n8k16.row.col.f32.bf16.bf16.f32 "
        "{%0,%1,%2,%3}, {%4,%5,%6,%7}, {%8,%9}, {%0,%1,%2,%3};"
        : "+f"(c[0]), "+f"(c[1]), "+f"(c[2]), "+f"(c[3])
        : "r"(a[0]), "r"(a[1]), "r"(a[2]), "r"(a[3]), "r"(b[0]), "r"(b[1]));
}

__device__ __forceinline__ void ldsm_x4(unsigned& r0, unsigned& r1,
                                        unsigned& r2, unsigned& r3, unsigned addr) {
    asm volatile("ldmatrix.sync.aligned.m8n8.x4.shared.b16 {%0,%1,%2,%3}, [%4];"
                 : "=r"(r0), "=r"(r1), "=r"(r2), "=r"(r3) : "r"(addr));
}

#define CP16(dst_u32, src_ptr) \
    asm volatile("cp.async.cg.shared.global [%0], [%1], 16;" \
                 :: "r"(dst_u32), "l"(src_ptr))
#define CP_COMMIT() asm volatile("cp.async.commit_group;")
#define CP_WAIT(n)  asm volatile("cp.async.wait_group %0;" :: "n"(n))

__device__ __forceinline__ void split_bf16(float v, __nv_bfloat16& hi, __nv_bfloat16& lo) {
    hi = __float2bfloat16_rn(v);
    lo = __float2bfloat16_rn(v - __bfloat162float(hi));
}

__global__ void __launch_bounds__(NTH, 1) __cluster_dims__(4, 1, 1) rnn_hmma(
    const float* __restrict__ x,
    const float* __restrict__ W_ih0, const float* __restrict__ W_hh0,
    const float* __restrict__ b_ih0, const float* __restrict__ b_hh0,
    const float* __restrict__ W_ih1, const float* __restrict__ W_hh1,
    const float* __restrict__ b_ih1, const float* __restrict__ b_hh1,
    const float* __restrict__ W_fc,  const float* __restrict__ b_fc,
    float* __restrict__ out)
{
    const int tid  = threadIdx.x;
    const int bid  = blockIdx.x;
    const int leaf = bid & 7;
    const int grp  = bid >> 5;
    const int ks   = bid & 3;
    const int tile = bid >> 2;
    const int mt   = tile >> 3;
    const int nt   = tile & 7;
    const int m0   = mt * TM;
    const int n0   = nt * TN;

    extern __shared__ __nv_bfloat16 sm[];
    float* scrA = (float*)(sm + ELEMS_TOT);
    float* scrB = (float*)(sm + OFF_AA_HI);      // aliases AA staging (dead in phase B)
    const unsigned sm_u32   = (unsigned)__cvta_generic_to_shared(sm);
    const unsigned scrA_u32 = sm_u32 + ELEMS_TOT * 2;
    const unsigned scrB_u32 = sm_u32 + OFF_AA_HI * 2;

    // ---------- distributed flag barrier state ----------
    unsigned stepno = 1;

    // ---------- one-time: split weight slices -> SMEM ----------
    {
        const int kb = ks * KA_PER;
        for (int idx = tid; idx < 64 * KA_PER; idx += NTH) {
            int n = idx / KA_PER, k = idx - n * KA_PER;
            int kg = kb + k;
            float v = (kg < DIN) ? W_ih0[(n0 + n) * DIN + kg]
                                 : W_hh0[(n0 + n) * HID + (kg - DIN)];
            __nv_bfloat16 hi, lo; split_bf16(v, hi, lo);
            sm[OFF_WA_HI + n * SA + k] = hi;
            sm[OFF_WA_LO + n * SA + k] = lo;
        }
        const int kbb = ks * KB_PER;
        for (int idx = tid; idx < 64 * KB_PER; idx += NTH) {
            int n = idx / KB_PER, k = idx - n * KB_PER;
            int kg = kbb + k;
            float v = (kg < HID) ? W_ih1[(n0 + n) * HID + kg]
                                 : W_hh1[(n0 + n) * HID + (kg - HID)];
            __nv_bfloat16 hi, lo; split_bf16(v, hi, lo);
            sm[OFF_WB_HI + n * SB + k] = hi;
            sm[OFF_WB_LO + n * SB + k] = lo;
        }
    }
    // ---------- one-time: pre-split x ----------
    {
        const int total = BATCH * SEQ * DIN;
        for (int i = (bid * NTH + tid) * 4; i < total; i += GRIDN * NTH * 4) {
            float4 v = *(const float4*)(x + i);
            __nv_bfloat16 h0,h1,h2,h3,l0,l1,l2,l3;
            split_bf16(v.x,h0,l0); split_bf16(v.y,h1,l1);
            split_bf16(v.z,h2,l2); split_bf16(v.w,h3,l3);
            *(__nv_bfloat162*)(g_Xhi + i)     = __halves2bfloat162(h0, h1);
            *(__nv_bfloat162*)(g_Xhi + i + 2) = __halves2bfloat162(h2, h3);
            *(__nv_bfloat162*)(g_Xlo + i)     = __halves2bfloat162(l0, l1);
            *(__nv_bfloat162*)(g_Xlo + i + 2) = __halves2bfloat162(l2, l3);
        }
    }
    // ---------- zero t=-1 states (buffer 1) ----------
    {
        const int per = (BATCH * HID) / GRIDN;
        const int base = bid * per;
        __nv_bfloat162 z = __halves2bfloat162(__float2bfloat16(0.f), __float2bfloat16(0.f));
        for (int i = tid * 2; i < per; i += NTH * 2) {
            *(__nv_bfloat162*)(&g_H1hi[1][base + i]) = z;
            *(__nv_bfloat162*)(&g_H1lo[1][base + i]) = z;
            *(__nv_bfloat162*)(&g_H2hi[1][base + i]) = z;
            *(__nv_bfloat162*)(&g_H2lo[1][base + i]) = z;
        }
    }
    grid_sync_init(leaf);

    // ---------- flag barrier: publish own step, watch group's 32 flags ----------
    auto group_flag_bar = [&]() {
        __syncthreads();
        if (tid == 0) {
            __threadfence();
            *(volatile unsigned*)&g_flag[bid].v = stepno;
        }
        if (tid < 32) {
            volatile unsigned* f = &g_flag[(grp << 5) + tid].v;
            while (*f < stepno) { __nanosleep(8); }
        }
        __syncthreads();
        __threadfence();
        stepno++;
    };

    // ---------- roles ----------
    const int lane = tid & 31;
    const int wid  = tid >> 5;
    const int wm   = wid & 1;
    const int wn   = (wid >> 1) & 1;
    const int wk   = wid >> 2;
    const int q    = lane >> 2;
    const int tg2  = (lane & 3) * 2;

    const int s_k   = lane * 8;
    const int s_row = wid;

    // ldmatrix lane offsets
    const int a_row = lane & 15;
    const int a_col = (lane & 16) >> 1;
    const int b_row = ((lane & 16) >> 1) + (lane & 7);
    const int b_col = lane & 8;

    // reduce role
    const int gtid = ks * NTH + tid;
    const int rr = gtid >> 4;
    const int cc = (gtid & 15) << 2;
    float4 biasA, biasB;
    {
        float4 bi = *(const float4*)(b_ih0 + n0 + cc);
        float4 bh = *(const float4*)(b_hh0 + n0 + cc);
        biasA = make_float4(bi.x+bh.x, bi.y+bh.y, bi.z+bh.z, bi.w+bh.w);
        bi = *(const float4*)(b_ih1 + n0 + cc);
        bh = *(const float4*)(b_hh1 + n0 + cc);
        biasB = make_float4(bi.x+bh.x, bi.y+bh.y, bi.z+bh.z, bi.w+bh.w);
    }
    const unsigned redoff = (unsigned)(rr * SCR_STRIDE + cc) * 4u;

    // ---------- async staging ----------
    auto stageA_async = [&](int t, const __nv_bfloat16* h1phi, const __nv_bfloat16* h1plo) {
        if (s_k < KA_PER) {
            const int kg = ks * KA_PER + s_k;
            #pragma unroll
            for (int it = 0; it < 8; ++it) {
                int row = s_row + it * 8;
                int mgr = m0 + row;
                const __nv_bfloat16 *ph, *pl;
                if (kg < DIN) {
                    size_t off = (size_t)mgr * (SEQ * DIN) + (size_t)t * DIN + kg;
                    ph = g_Xhi + off; pl = g_Xlo + off;
                } else {
                    size_t off = (size_t)mgr * HID + (kg - DIN);
                    ph = h1phi + off; pl = h1plo + off;
                }
                CP16(sm_u32 + (OFF_AA_HI + row * SA + s_k) * 2, ph);
                CP16(sm_u32 + (OFF_AA_LO + row * SA + s_k) * 2, pl);
            }
        }
        CP_COMMIT();
    };
    auto stageB_async = [&](const __nv_bfloat16* h1phi, const __nv_bfloat16* h1plo,
                            const __nv_bfloat16* h2phi, const __nv_bfloat16* h2plo) {
        const int kg = ks * KB_PER + s_k;
        const int koff = (ks < 2) ? kg : kg - HID;
        const __nv_bfloat16* shi = (ks < 2) ? h1phi : h2phi;
        const __nv_bfloat16* slo = (ks < 2) ? h1plo : h2plo;
        #pragma unroll
        for (int it = 0; it < 8; ++it) {
            int row = s_row + it * 8;
            size_t off = (size_t)(m0 + row) * HID + koff;
            CP16(sm_u32 + (OFF_AB_HI + row * SB + s_k) * 2, shi + off);
            CP16(sm_u32 + (OFF_AB_LO + row * SB + s_k) * 2, slo + off);
        }
        CP_COMMIT();
    };

    // ---------- GEMM phase: 3-split HMMA via ldmatrix; k-halves merged into scrp ----------
    auto computePhase = [&](int offWhi, int offWlo, int offAhi, int offAlo, int st,
                            int ks0, int ks1, float* __restrict__ scrp) {
        float acc[2][4][4];
        #pragma unroll
        for (int f = 0; f < 2; f++)
            #pragma unroll
            for (int g = 0; g < 4; g++)
                #pragma unroll
                for (int i = 0; i < 4; i++) acc[f][g][i] = 0.f;

        unsigned aHiB[2], aLoB[2], bHiB[2], bLoB[2];
        #pragma unroll
        for (int f = 0; f < 2; f++) {
            unsigned roff = (unsigned)((wm * 32 + f * 16 + a_row) * st + a_col);
            aHiB[f] = sm_u32 + (offAhi + roff) * 2;
            aLoB[f] = sm_u32 + (offAlo + roff) * 2;
        }
        #pragma unroll
        for (int p = 0; p < 2; p++) {
            unsigned roff = (unsigned)((wn * 32 + p * 16 + b_row) * st + b_col);
            bHiB[p] = sm_u32 + (offWhi + roff) * 2;
            bLoB[p] = sm_u32 + (offWlo + roff) * 2;
        }

        for (int kst = ks0; kst < ks1; ++kst) {
            const unsigned kadv = (unsigned)(kst * 16) * 2;
            unsigned ah[2][4], al[2][4], bh[4][2], bl[4][2];
            #pragma unroll
            for (int f = 0; f < 2; f++) {
                ldsm_x4(ah[f][0], ah[f][1], ah[f][2], ah[f][3], aHiB[f] + kadv);
                ldsm_x4(al[f][0], al[f][1], al[f][2], al[f][3], aLoB[f] + kadv);
            }
            #pragma unroll
            for (int p = 0; p < 2; p++) {
                ldsm_x4(bh[2*p][0], bh[2*p][1], bh[2*p+1][0], bh[2*p+1][1], bHiB[p] + kadv);
                ldsm_x4(bl[2*p][0], bl[2*p][1], bl[2*p+1][0], bl[2*p+1][1], bLoB[p] + kadv);
            }
            #pragma unroll
            for (int f = 0; f < 2; f++)
                #pragma unroll
                for (int g = 0; g < 4; g++) {
                    mma16816(acc[f][g], ah[f], bh[g]);
                    mma16816(acc[f][g], al[f], bh[g]);
                    mma16816(acc[f][g], ah[f], bl[g]);
                }
        }
        if (wk == 1) {
            #pragma unroll
            for (int f = 0; f < 2; f++)
                #pragma unroll
                for (int g = 0; g < 4; g++) {
                    int r = wm * 32 + f * 16 + q;
                    int c = wn * 32 + g * 8 + tg2;
                    *(float2*)(scrp + r * SCR_STRIDE + c) =
                        make_float2(acc[f][g][0], acc[f][g][1]);
                    *(float2*)(scrp + (r + 8) * SCR_STRIDE + c) =
                        make_float2(acc[f][g][2], acc[f][g][3]);
                }
        }
        __syncthreads();
        if (wk == 0) {
            #pragma unroll
            for (int f = 0; f < 2; f++)
                #pragma unroll
                for (int g = 0; g < 4; g++) {
                    int r = wm * 32 + f * 16 + q;
                    int c = wn * 32 + g * 8 + tg2;
                    float2 o0 = *(const float2*)(scrp + r * SCR_STRIDE + c);
                    float2 o1 = *(const float2*)(scrp + (r + 8) * SCR_STRIDE + c);
                    *(float2*)(scrp + r * SCR_STRIDE + c) =
                        make_float2(acc[f][g][0] + o0.x, acc[f][g][1] + o0.y);
                    *(float2*)(scrp + (r + 8) * SCR_STRIDE + c) =
                        make_float2(acc[f][g][2] + o1.x, acc[f][g][3] + o1.y);
                }
        }
    };

    // tanh + split + store helper
    auto finishH = [&](float4 s, __nv_bfloat16* __restrict__ dhi,
                       __nv_bfloat16* __restrict__ dlo) {
        float h0 = tanhf(s.x), h1 = tanhf(s.y), h2 = tanhf(s.z), h3 = tanhf(s.w);
        __nv_bfloat16 hi0,hi1,hi2,hi3, lo0,lo1,lo2,lo3;
        split_bf16(h0,hi0,lo0); split_bf16(h1,hi1,lo1);
        split_bf16(h2,hi2,lo2); split_bf16(h3,hi3,lo3);
        __nv_bfloat162 ph0 = __halves2bfloat162(hi0,hi1), ph1 = __halves2bfloat162(hi2,hi3);
        __nv_bfloat162 pl0 = __halves2bfloat162(lo0,lo1), pl1 = __halves2bfloat162(lo2,lo3);
        uint2 uh, ul;
        uh.x = *(unsigned*)&ph0; uh.y = *(unsigned*)&ph1;
        ul.x = *(unsigned*)&pl0; ul.y = *(unsigned*)&pl1;
        size_t doff = (size_t)(m0 + rr) * HID + n0 + cc;
        __stcg((uint2*)(dhi + doff), uh);
        __stcg((uint2*)(dlo + doff), ul);
    };

    // merged reduce: all 8 DSMEM loads first (MLP 8), then tanh + stores
    auto reduceAB = [&](bool doB,
                        __nv_bfloat16* d1hi, __nv_bfloat16* d1lo,
                        __nv_bfloat16* d2hi, __nv_bfloat16* d2lo) {
        const unsigned aA = scrA_u32 + redoff;
        const unsigned aB = scrB_u32 + redoff;
        float4 a0 = ld_dsmem_f4(mapa_rank(aA, 0));
        float4 a1 = ld_dsmem_f4(mapa_rank(aA, 1));
        float4 a2 = ld_dsmem_f4(mapa_rank(aA, 2));
        float4 a3 = ld_dsmem_f4(mapa_rank(aA, 3));
        float4 b0, b1, b2, b3;
        if (doB) {
            b0 = ld_dsmem_f4(mapa_rank(aB, 0));
            b1 = ld_dsmem_f4(mapa_rank(aB, 1));
            b2 = ld_dsmem_f4(mapa_rank(aB, 2));
            b3 = ld_dsmem_f4(mapa_rank(aB, 3));
        }
        float4 s;
        s.x = biasA.x + a0.x + a1.x + a2.x + a3.x;
        s.y = biasA.y + a0.y + a1.y + a2.y + a3.y;
        s.z = biasA.z + a0.z + a1.z + a2.z + a3.z;
        s.w = biasA.w + a0.w + a1.w + a2.w + a3.w;
        finishH(s, d1hi, d1lo);
        if (doB) {
            s.x = biasB.x + b0.x + b1.x + b2.x + b3.x;
            s.y = biasB.y + b0.y + b1.y + b2.y + b3.y;
            s.z = biasB.z + b0.z + b1.z + b2.z + b3.z;
            s.w = biasB.w + b0.w + b1.w + b2.w + b3.w;
            finishH(s, d2hi, d2lo);
        }
    };

    const int ksA0 = wk ? 5 : 0, ksA1 = wk ? 9 : 5;
    const int ksB0 = wk ? 8 : 0, ksB1 = wk ? 16 : 8;

    // ============================ main loop ============================
    for (int t = 0; t < SEQ; ++t) {
        const int pp = (t + 1) & 1, pc = t & 1;
        const __nv_bfloat16* h1phi = g_H1hi[pp]; const __nv_bfloat16* h1plo = g_H1lo[pp];
        const __nv_bfloat16* h2phi = g_H2hi[pc]; const __nv_bfloat16* h2plo = g_H2lo[pc];

        stageA_async(t, h1phi, h1plo);
        if (t > 0) {
            stageB_async(h1phi, h1plo, h2phi, h2plo);
            CP_WAIT(1);
        } else {
            CP_WAIT(0);
        }
        __syncthreads();
        computePhase(OFF_WA_HI, OFF_WA_LO, OFF_AA_HI, OFF_AA_LO, SA, ksA0, ksA1, scrA);
        if (t > 0) {
            CP_WAIT(0);
            __syncthreads();
            computePhase(OFF_WB_HI, OFF_WB_LO, OFF_AB_HI, OFF_AB_LO, SB, ksB0, ksB1, scrB);
        }
        CLUSTER_SYNC();
        reduceAB(t > 0, g_H1hi[pc], g_H1lo[pc], g_H2hi[pp], g_H2lo[pp]);
        group_flag_bar();
    }
    // epilogue: B(511): h1(511) in buf1, h2(510) in buf0 -> h2(511) in buf1
    stageB_async(g_H1hi[1], g_H1lo[1], g_H2hi[0], g_H2lo[0]);
    CP_WAIT(0);
    __syncthreads();
    computePhase(OFF_WB_HI, OFF_WB_LO, OFF_AB_HI, OFF_AB_LO, SB, ksB0, ksB1, scrB);
    CLUSTER_SYNC();
    {
        const unsigned aB = scrB_u32 + redoff;
        float4 b0 = ld_dsmem_f4(mapa_rank(aB, 0));
        float4 b1 = ld_dsmem_f4(mapa_rank(aB, 1));
        float4 b2 = ld_dsmem_f4(mapa_rank(aB, 2));
        float4 b3 = ld_dsmem_f4(mapa_rank(aB, 3));
        float4 s;
        s.x = biasB.x + b0.x + b1.x + b2.x + b3.x;
        s.y = biasB.y + b0.y + b1.y + b2.y + b3.y;
        s.z = biasB.z + b0.z + b1.z + b2.z + b3.z;
        s.w = biasB.w + b0.w + b1.w + b2.w + b3.w;
        finishH(s, g_H2hi[1], g_H2lo[1]);
    }
    group_flag_bar();

    // ============================ final FC ============================
    static __shared__ float red[8];
    for (int r = 0; r < 2; ++r) {
        int b = bid * 2 + r;
        float s = 0.f;
        for (int h = tid * 2; h < HID; h += NTH * 2) {
            unsigned uh = __ldcg((const unsigned*)(&g_H2hi[1][(size_t)b * HID + h]));
            unsigned ul = __ldcg((const unsigned*)(&g_H2lo[1][(size_t)b * HID + h]));
            __nv_bfloat162 vh = *(__nv_bfloat162*)&uh;
            __nv_bfloat162 vl = *(__nv_bfloat162*)&ul;
            float v0 = __bfloat162float(__low2bfloat16(vh)) + __bfloat162float(__low2bfloat16(vl));
            float v1 = __bfloat162float(__high2bfloat16(vh)) + __bfloat162float(__high2bfloat16(vl));
            s += v0 * W_fc[h] + v1 * W_fc[h + 1];
        }
        #pragma unroll
        for (int off = 16; off; off >>= 1)
            s += __shfl_down_sync(0xffffffffu, s, off);
        if ((tid & 31) == 0) red[tid >> 5] = s;
        __syncthreads();
        if (tid == 0) {
            float tot = b_fc[0];
            #pragma unroll
            for (int w = 0; w < 8; w++) tot += red[w];
            out[b] = tot;
        }
        __syncthreads();
    }
}

extern "C" void kernel_launch(void* const* d_in, const int* in_sizes, int n_in,
                              void* d_out, int out_size) {
    (void)in_sizes; (void)n_in; (void)out_size;
    const float* x     = (const float*)d_in[0];
    const float* W_ih0 = (const float*)d_in[1];
    const float* W_hh0 = (const float*)d_in[2];
    const float* b_ih0 = (const float*)d_in[3];
    const float* b_hh0 = (const float*)d_in[4];
    const float* W_ih1 = (const float*)d_in[5];
    const float* W_hh1 = (const float*)d_in[6];
    const float* b_ih1 = (const float*)d_in[7];
    const float* b_hh1 = (const float*)d_in[8];
    const float* W_fc  = (const float*)d_in[9];
    const float* b_fc  = (const float*)d_in[10];
    float* out = (float*)d_out;

    cudaFuncSetAttribute(rnn_hmma,
                         cudaFuncAttributeMaxDynamicSharedMemorySize, SMEM_BYTES);
    rnn_hmma<<<GRIDN, NTH, SMEM_BYTES>>>(
        x, W_ih0, W_hh0, b_ih0, b_hh0,
        W_ih1, W_hh1, b_ih1, b_hh1, W_fc, b_fc, out);
}

// round 14
// speedup vs baseline: 1.4920x; 1.0500x over previous
#include <cuda_runtime.h>
#include <cuda_bf16.h>
#include <cstddef>

#define BATCH 256
#define SEQ   512
#define DIN   64
#define HID   512
#define GRIDN 128
#define NTH   256

#define TM 64
#define TN 64
#define KA_PER 144          // 576 / 4
#define KB_PER 256          // 1024 / 4
#define NC_A 9
#define NC_B 16

#define SA 152              // A-phase row stride (bf16 elems)
#define SB 264              // B-phase row stride

#define OFF_WA_HI 0
#define OFF_WA_LO (OFF_WA_HI + 64 * SA)
#define OFF_AA_HI (OFF_WA_LO + 64 * SA)
#define OFF_AA_LO (OFF_AA_HI + 64 * SA)
#define OFF_WB_HI (OFF_AA_LO + 64 * SA)
#define OFF_WB_LO (OFF_WB_HI + 64 * SB)
#define OFF_AB_HI (OFF_WB_LO + 64 * SB)
#define OFF_AB_LO (OFF_AB_HI + 64 * SB)
#define ELEMS_TOT (OFF_AB_LO + 64 * SB)          // 106,496 bf16 = 212,992 B
#define SCR_STRIDE 68                            // fp32; rows 16B-aligned
#define SMEM_BYTES (ELEMS_TOT * 2 + 64 * SCR_STRIDE * 4)   // 230,400 B

typedef unsigned long long ull;

// ---------------- cross-CTA state (static scratch; allocation-free) ----------------
__device__ __nv_bfloat16 g_Xhi[BATCH * SEQ * DIN];
__device__ __nv_bfloat16 g_Xlo[BATCH * SEQ * DIN];
__device__ __nv_bfloat16 g_H1hi[2][BATCH * HID], g_H1lo[2][BATCH * HID];
__device__ __nv_bfloat16 g_H2hi[2][BATCH * HID], g_H2lo[2][BATCH * HID];

struct __align__(128) Line { unsigned v; unsigned pad[31]; };
__device__ Line g_leaf[8];
__device__ Line g_root;
__device__ Line g_gen;
__device__ Line g_flag[GRIDN];   // per-CTA step flags (zero-init)

// full-grid tree barrier (init only)
__device__ __forceinline__ void grid_sync_init(int leaf) {
    __syncthreads();
    if (threadIdx.x == 0) {
        unsigned gen = *(volatile unsigned*)&g_gen.v;
        __threadfence();
        if (atomicAdd(&g_leaf[leaf].v, 1u) == 15u) {
            g_leaf[leaf].v = 0u;
            __threadfence();
            if (atomicAdd(&g_root.v, 1u) == 7u) {
                g_root.v = 0u;
                __threadfence();
                *(volatile unsigned*)&g_gen.v = gen + 1u;
            } else {
                while (*(volatile unsigned*)&g_gen.v == gen) __nanosleep(16);
            }
        } else {
            while (*(volatile unsigned*)&g_gen.v == gen) __nanosleep(16);
        }
        __threadfence();
    }
    __syncthreads();
}

#define CLUSTER_SYNC() do { \
    asm volatile("barrier.cluster.arrive.aligned;" ::: "memory"); \
    asm volatile("barrier.cluster.wait.aligned;" ::: "memory"); \
} while (0)

__device__ __forceinline__ unsigned mapa_rank(unsigned smaddr, unsigned rank) {
    unsigned r;
    asm("mapa.shared::cluster.u32 %0, %1, %2;" : "=r"(r) : "r"(smaddr), "r"(rank));
    return r;
}
__device__ __forceinline__ float4 ld_dsmem_f4(unsigned addr) {
    float4 v;
    asm volatile("ld.shared::cluster.v4.f32 {%0,%1,%2,%3}, [%4];"
                 : "=f"(v.x), "=f"(v.y), "=f"(v.z), "=f"(v.w) : "r"(addr));
    return v;
}

__device__ __forceinline__ void mma16816(float* c, const unsigned* a, const unsigned* b) {
    asm volatile(
        "mma.sync.aligned.m16n8k16.row.col.f32.bf16.bf16.f32 "
        "{%0,%1,%2,%3}, {%4,%5,%6,%7}, {%8,%9}, {%0,%1,%2,%3};"
        : "+f"(c[0]), "+f"(c[1]), "+f"(c[2]), "+f"(c[3])
        : "r"(a[0]), "r"(a[1]), "r"(a[2]), "r"(a[3]), "r"(b[0]), "r"(b[1]));
}

__device__ __forceinline__ void ldsm_x4(unsigned& r0, unsigned& r1,
                                        unsigned& r2, unsigned& r3, unsigned addr) {
    asm volatile("ldmatrix.sync.aligned.m8n8.x4.shared.b16 {%0,%1,%2,%3}, [%4];"
                 : "=r"(r0), "=r"(r1), "=r"(r2), "=r"(r3) : "r"(addr));
}

#define CP16(dst_u32, src_ptr) \
    asm volatile("cp.async.cg.shared.global [%0], [%1], 16;" \
                 :: "r"(dst_u32), "l"(src_ptr))
#define CP_COMMIT() asm volatile("cp.async.commit_group;")
#define CP_WAIT(n)  asm volatile("cp.async.wait_group %0;" :: "n"(n))

__device__ __forceinline__ void split_bf16(float v, __nv_bfloat16& hi, __nv_bfloat16& lo) {
    hi = __float2bfloat16_rn(v);
    lo = __float2bfloat16_rn(v - __bfloat162float(hi));
}

__global__ void __launch_bounds__(NTH, 1) __cluster_dims__(4, 1, 1) rnn_hmma(
    const float* __restrict__ x,
    const float* __restrict__ W_ih0, const float* __restrict__ W_hh0,
    const float* __restrict__ b_ih0, const float* __restrict__ b_hh0,
    const float* __restrict__ W_ih1, const float* __restrict__ W_hh1,
    const float* __restrict__ b_ih1, const float* __restrict__ b_hh1,
    const float* __restrict__ W_fc,  const float* __restrict__ b_fc,
    float* __restrict__ out)
{
    const int tid  = threadIdx.x;
    const int bid  = blockIdx.x;
    const int leaf = bid & 7;
    const int grp  = bid >> 5;
    const int ks   = bid & 3;
    const int tile = bid >> 2;
    const int mt   = tile >> 3;
    const int nt   = tile & 7;
    const int m0   = mt * TM;
    const int n0   = nt * TN;

    extern __shared__ __nv_bfloat16 sm[];
    float* scrA = (float*)(sm + ELEMS_TOT);
    float* scrB = (float*)(sm + OFF_AA_HI);      // aliases AA staging (dead in phase B)
    const unsigned sm_u32   = (unsigned)__cvta_generic_to_shared(sm);
    const unsigned scrA_u32 = sm_u32 + ELEMS_TOT * 2;
    const unsigned scrB_u32 = sm_u32 + OFF_AA_HI * 2;

    unsigned stepno = 1;

    // ---------- one-time: split weight slices -> SMEM ----------
    {
        const int kb = ks * KA_PER;
        for (int idx = tid; idx < 64 * KA_PER; idx += NTH) {
            int n = idx / KA_PER, k = idx - n * KA_PER;
            int kg = kb + k;
            float v = (kg < DIN) ? W_ih0[(n0 + n) * DIN + kg]
                                 : W_hh0[(n0 + n) * HID + (kg - DIN)];
            __nv_bfloat16 hi, lo; split_bf16(v, hi, lo);
            sm[OFF_WA_HI + n * SA + k] = hi;
            sm[OFF_WA_LO + n * SA + k] = lo;
        }
        const int kbb = ks * KB_PER;
        for (int idx = tid; idx < 64 * KB_PER; idx += NTH) {
            int n = idx / KB_PER, k = idx - n * KB_PER;
            int kg = kbb + k;
            float v = (kg < HID) ? W_ih1[(n0 + n) * HID + kg]
                                 : W_hh1[(n0 + n) * HID + (kg - HID)];
            __nv_bfloat16 hi, lo; split_bf16(v, hi, lo);
            sm[OFF_WB_HI + n * SB + k] = hi;
            sm[OFF_WB_LO + n * SB + k] = lo;
        }
    }
    // ---------- one-time: pre-split x ----------
    {
        const int total = BATCH * SEQ * DIN;
        for (int i = (bid * NTH + tid) * 4; i < total; i += GRIDN * NTH * 4) {
            float4 v = *(const float4*)(x + i);
            __nv_bfloat16 h0,h1,h2,h3,l0,l1,l2,l3;
            split_bf16(v.x,h0,l0); split_bf16(v.y,h1,l1);
            split_bf16(v.z,h2,l2); split_bf16(v.w,h3,l3);
            *(__nv_bfloat162*)(g_Xhi + i)     = __halves2bfloat162(h0, h1);
            *(__nv_bfloat162*)(g_Xhi + i + 2) = __halves2bfloat162(h2, h3);
            *(__nv_bfloat162*)(g_Xlo + i)     = __halves2bfloat162(l0, l1);
            *(__nv_bfloat162*)(g_Xlo + i + 2) = __halves2bfloat162(l2, l3);
        }
    }
    // ---------- zero t=-1 states (buffer 1) ----------
    {
        const int per = (BATCH * HID) / GRIDN;
        const int base = bid * per;
        __nv_bfloat162 z = __halves2bfloat162(__float2bfloat16(0.f), __float2bfloat16(0.f));
        for (int i = tid * 2; i < per; i += NTH * 2) {
            *(__nv_bfloat162*)(&g_H1hi[1][base + i]) = z;
            *(__nv_bfloat162*)(&g_H1lo[1][base + i]) = z;
            *(__nv_bfloat162*)(&g_H2hi[1][base + i]) = z;
            *(__nv_bfloat162*)(&g_H2lo[1][base + i]) = z;
        }
    }
    grid_sync_init(leaf);

    // ---------- flag barrier ----------
    auto group_flag_bar = [&]() {
        __syncthreads();
        if (tid == 0) {
            __threadfence();
            *(volatile unsigned*)&g_flag[bid].v = stepno;
        }
        if (tid < 32) {
            volatile unsigned* f = &g_flag[(grp << 5) + tid].v;
            while (*f < stepno) { __nanosleep(8); }
        }
        __syncthreads();
        __threadfence();
        stepno++;
    };

    // ---------- roles ----------
    const int lane = tid & 31;
    const int wid  = tid >> 5;
    const int wm   = wid >> 2;        // m-half (0/1)
    const int wn4  = wid & 3;         // n-quarter (0..3), 16 cols each
    const int q    = lane >> 2;
    const int tg2  = (lane & 3) * 2;

    const int s_k   = lane * 8;
    const int s_row = wid;

    // ldmatrix lane offsets
    const int a_row = lane & 15;
    const int a_col = (lane & 16) >> 1;
    const int b_row = ((lane & 16) >> 1) + (lane & 7);
    const int b_col = lane & 8;

    // reduce role
    const int gtid = ks * NTH + tid;
    const int rr = gtid >> 4;
    const int cc = (gtid & 15) << 2;
    float4 biasA, biasB;
    {
        float4 bi = *(const float4*)(b_ih0 + n0 + cc);
        float4 bh = *(const float4*)(b_hh0 + n0 + cc);
        biasA = make_float4(bi.x+bh.x, bi.y+bh.y, bi.z+bh.z, bi.w+bh.w);
        bi = *(const float4*)(b_ih1 + n0 + cc);
        bh = *(const float4*)(b_hh1 + n0 + cc);
        biasB = make_float4(bi.x+bh.x, bi.y+bh.y, bi.z+bh.z, bi.w+bh.w);
    }
    const unsigned redoff = (unsigned)(rr * SCR_STRIDE + cc) * 4u;

    // ---------- async staging ----------
    auto stageA_async = [&](int t, const __nv_bfloat16* h1phi, const __nv_bfloat16* h1plo) {
        if (s_k < KA_PER) {
            const int kg = ks * KA_PER + s_k;
            #pragma unroll
            for (int it = 0; it < 8; ++it) {
                int row = s_row + it * 8;
                int mgr = m0 + row;
                const __nv_bfloat16 *ph, *pl;
                if (kg < DIN) {
                    size_t off = (size_t)mgr * (SEQ * DIN) + (size_t)t * DIN + kg;
                    ph = g_Xhi + off; pl = g_Xlo + off;
                } else {
                    size_t off = (size_t)mgr * HID + (kg - DIN);
                    ph = h1phi + off; pl = h1plo + off;
                }
                CP16(sm_u32 + (OFF_AA_HI + row * SA + s_k) * 2, ph);
                CP16(sm_u32 + (OFF_AA_LO + row * SA + s_k) * 2, pl);
            }
        }
        CP_COMMIT();
    };
    auto stageB_async = [&](const __nv_bfloat16* h1phi, const __nv_bfloat16* h1plo,
                            const __nv_bfloat16* h2phi, const __nv_bfloat16* h2plo) {
        const int kg = ks * KB_PER + s_k;
        const int koff = (ks < 2) ? kg : kg - HID;
        const __nv_bfloat16* shi = (ks < 2) ? h1phi : h2phi;
        const __nv_bfloat16* slo = (ks < 2) ? h1plo : h2plo;
        #pragma unroll
        for (int it = 0; it < 8; ++it) {
            int row = s_row + it * 8;
            size_t off = (size_t)(m0 + row) * HID + koff;
            CP16(sm_u32 + (OFF_AB_HI + row * SB + s_k) * 2, shi + off);
            CP16(sm_u32 + (OFF_AB_LO + row * SB + s_k) * 2, slo + off);
        }
        CP_COMMIT();
    };

    // ---------- GEMM phase: full-K per warp (2m x 4n), direct scr store ----------
    auto computePhase = [&](int offWhi, int offWlo, int offAhi, int offAlo, int st,
                            int NC, float* __restrict__ scrp) {
        float acc[2][2][4];
        #pragma unroll
        for (int f = 0; f < 2; f++)
            #pragma unroll
            for (int g = 0; g < 2; g++)
                #pragma unroll
                for (int i = 0; i < 4; i++) acc[f][g][i] = 0.f;

        unsigned aHiB[2], aLoB[2], bHiB, bLoB;
        #pragma unroll
        for (int f = 0; f < 2; f++) {
            unsigned roff = (unsigned)((wm * 32 + f * 16 + a_row) * st + a_col);
            aHiB[f] = sm_u32 + (offAhi + roff) * 2;
            aLoB[f] = sm_u32 + (offAlo + roff) * 2;
        }
        {
            unsigned roff = (unsigned)((wn4 * 16 + b_row) * st + b_col);
            bHiB = sm_u32 + (offWhi + roff) * 2;
            bLoB = sm_u32 + (offWlo + roff) * 2;
        }

        #pragma unroll 4
        for (int kst = 0; kst < NC; ++kst) {
            const unsigned kadv = (unsigned)kst * 32u;   // 16 elems * 2 bytes
            unsigned ah[2][4], al[2][4], bh[2][2], bl[2][2];
            #pragma unroll
            for (int f = 0; f < 2; f++) {
                ldsm_x4(ah[f][0], ah[f][1], ah[f][2], ah[f][3], aHiB[f] + kadv);
                ldsm_x4(al[f][0], al[f][1], al[f][2], al[f][3], aLoB[f] + kadv);
            }
            ldsm_x4(bh[0][0], bh[0][1], bh[1][0], bh[1][1], bHiB + kadv);
            ldsm_x4(bl[0][0], bl[0][1], bl[1][0], bl[1][1], bLoB + kadv);
            #pragma unroll
            for (int f = 0; f < 2; f++)
                #pragma unroll
                for (int g = 0; g < 2; g++) {
                    mma16816(acc[f][g], ah[f], bh[g]);
                    mma16816(acc[f][g], al[f], bh[g]);
                    mma16816(acc[f][g], ah[f], bl[g]);
                }
        }
        // direct store: warp owns rows wm*32..+31, cols wn4*16..+15
        #pragma unroll
        for (int f = 0; f < 2; f++)
            #pragma unroll
            for (int g = 0; g < 2; g++) {
                int r = wm * 32 + f * 16 + q;
                int c = wn4 * 16 + g * 8 + tg2;
                *(float2*)(scrp + r * SCR_STRIDE + c) =
                    make_float2(acc[f][g][0], acc[f][g][1]);
                *(float2*)(scrp + (r + 8) * SCR_STRIDE + c) =
                    make_float2(acc[f][g][2], acc[f][g][3]);
            }
    };

    // tanh + split + store helper
    auto finishH = [&](float4 s, __nv_bfloat16* __restrict__ dhi,
                       __nv_bfloat16* __restrict__ dlo) {
        float h0 = tanhf(s.x), h1 = tanhf(s.y), h2 = tanhf(s.z), h3 = tanhf(s.w);
        __nv_bfloat16 hi0,hi1,hi2,hi3, lo0,lo1,lo2,lo3;
        split_bf16(h0,hi0,lo0); split_bf16(h1,hi1,lo1);
        split_bf16(h2,hi2,lo2); split_bf16(h3,hi3,lo3);
        __nv_bfloat162 ph0 = __halves2bfloat162(hi0,hi1), ph1 = __halves2bfloat162(hi2,hi3);
        __nv_bfloat162 pl0 = __halves2bfloat162(lo0,lo1), pl1 = __halves2bfloat162(lo2,lo3);
        uint2 uh, ul;
        uh.x = *(unsigned*)&ph0; uh.y = *(unsigned*)&ph1;
        ul.x = *(unsigned*)&pl0; ul.y = *(unsigned*)&pl1;
        size_t doff = (size_t)(m0 + rr) * HID + n0 + cc;
        __stcg((uint2*)(dhi + doff), uh);
        __stcg((uint2*)(dlo + doff), ul);
    };

    // merged reduce: all 8 DSMEM loads first (MLP 8), then tanh + stores
    auto reduceAB = [&](bool doB,
                        __nv_bfloat16* d1hi, __nv_bfloat16* d1lo,
                        __nv_bfloat16* d2hi, __nv_bfloat16* d2lo) {
        const unsigned aA = scrA_u32 + redoff;
        const unsigned aB = scrB_u32 + redoff;
        float4 a0 = ld_dsmem_f4(mapa_rank(aA, 0));
        float4 a1 = ld_dsmem_f4(mapa_rank(aA, 1));
        float4 a2 = ld_dsmem_f4(mapa_rank(aA, 2));
        float4 a3 = ld_dsmem_f4(mapa_rank(aA, 3));
        float4 b0, b1, b2, b3;
        if (doB) {
            b0 = ld_dsmem_f4(mapa_rank(aB, 0));
            b1 = ld_dsmem_f4(mapa_rank(aB, 1));
            b2 = ld_dsmem_f4(mapa_rank(aB, 2));
            b3 = ld_dsmem_f4(mapa_rank(aB, 3));
        }
        float4 s;
        s.x = biasA.x + a0.x + a1.x + a2.x + a3.x;
        s.y = biasA.y + a0.y + a1.y + a2.y + a3.y;
        s.z = biasA.z + a0.z + a1.z + a2.z + a3.z;
        s.w = biasA.w + a0.w + a1.w + a2.w + a3.w;
        finishH(s, d1hi, d1lo);
        if (doB) {
            s.x = biasB.x + b0.x + b1.x + b2.x + b3.x;
            s.y = biasB.y + b0.y + b1.y + b2.y + b3.y;
            s.z = biasB.z + b0.z + b1.z + b2.z + b3.z;
            s.w = biasB.w + b0.w + b1.w + b2.w + b3.w;
            finishH(s, d2hi, d2lo);
        }
    };

    // ============================ main loop ============================
    for (int t = 0; t < SEQ; ++t) {
        const int pp = (t + 1) & 1, pc = t & 1;
        const __nv_bfloat16* h1phi = g_H1hi[pp]; const __nv_bfloat16* h1plo = g_H1lo[pp];
        const __nv_bfloat16* h2phi = g_H2hi[pc]; const __nv_bfloat16* h2plo = g_H2lo[pc];

        stageA_async(t, h1phi, h1plo);
        if (t > 0) {
            stageB_async(h1phi, h1plo, h2phi, h2plo);
            CP_WAIT(1);
        } else {
            CP_WAIT(0);
        }
        __syncthreads();
        computePhase(OFF_WA_HI, OFF_WA_LO, OFF_AA_HI, OFF_AA_LO, SA, NC_A, scrA);
        if (t > 0) {
            CP_WAIT(0);
            __syncthreads();               // AB staged visible; all warps past computeA
            computePhase(OFF_WB_HI, OFF_WB_LO, OFF_AB_HI, OFF_AB_LO, SB, NC_B, scrB);
        }
        CLUSTER_SYNC();                    // scrA + scrB visible cluster-wide
        reduceAB(t > 0, g_H1hi[pc], g_H1lo[pc], g_H2hi[pp], g_H2lo[pp]);
        group_flag_bar();
    }
    // epilogue: B(511): h1(511) in buf1, h2(510) in buf0 -> h2(511) in buf1
    stageB_async(g_H1hi[1], g_H1lo[1], g_H2hi[0], g_H2lo[0]);
    CP_WAIT(0);
    __syncthreads();
    computePhase(OFF_WB_HI, OFF_WB_LO, OFF_AB_HI, OFF_AB_LO, SB, NC_B, scrB);
    CLUSTER_SYNC();
    {
        const unsigned aB = scrB_u32 + redoff;
        float4 b0 = ld_dsmem_f4(mapa_rank(aB, 0));
        float4 b1 = ld_dsmem_f4(mapa_rank(aB, 1));
        float4 b2 = ld_dsmem_f4(mapa_rank(aB, 2));
        float4 b3 = ld_dsmem_f4(mapa_rank(aB, 3));
        float4 s;
        s.x = biasB.x + b0.x + b1.x + b2.x + b3.x;
        s.y = biasB.y + b0.y + b1.y + b2.y + b3.y;
        s.z = biasB.z + b0.z + b1.z + b2.z + b3.z;
        s.w = biasB.w + b0.w + b1.w + b2.w + b3.w;
        finishH(s, g_H2hi[1], g_H2lo[1]);
    }
    group_flag_bar();

    // ============================ final FC ============================
    static __shared__ float red[8];
    for (int r = 0; r < 2; ++r) {
        int b = bid * 2 + r;
        float s = 0.f;
        for (int h = tid * 2; h < HID; h += NTH * 2) {
            unsigned uh = __ldcg((const unsigned*)(&g_H2hi[1][(size_t)b * HID + h]));
            unsigned ul = __ldcg((const unsigned*)(&g_H2lo[1][(size_t)b * HID + h]));
            __nv_bfloat162 vh = *(__nv_bfloat162*)&uh;
            __nv_bfloat162 vl = *(__nv_bfloat162*)&ul;
            float v0 = __bfloat162float(__low2bfloat16(vh)) + __bfloat162float(__low2bfloat16(vl));
            float v1 = __bfloat162float(__high2bfloat16(vh)) + __bfloat162float(__high2bfloat16(vl));
            s += v0 * W_fc[h] + v1 * W_fc[h + 1];
        }
        #pragma unroll
        for (int off = 16; off; off >>= 1)
            s += __shfl_down_sync(0xffffffffu, s, off);
        if ((tid & 31) == 0) red[tid >> 5] = s;
        __syncthreads();
        if (tid == 0) {
            float tot = b_fc[0];
            #pragma unroll
            for (int w = 0; w < 8; w++) tot += red[w];
            out[b] = tot;
        }
        __syncthreads();
    }
}

extern "C" void kernel_launch(void* const* d_in, const int* in_sizes, int n_in,
                              void* d_out, int out_size) {
    (void)in_sizes; (void)n_in; (void)out_size;
    const float* x     = (const float*)d_in[0];
    const float* W_ih0 = (const float*)d_in[1];
    const float* W_hh0 = (const float*)d_in[2];
    const float* b_ih0 = (const float*)d_in[3];
    const float* b_hh0 = (const float*)d_in[4];
    const float* W_ih1 = (const float*)d_in[5];
    const float* W_hh1 = (const float*)d_in[6];
    const float* b_ih1 = (const float*)d_in[7];
    const float* b_hh1 = (const float*)d_in[8];
    const float* W_fc  = (const float*)d_in[9];
    const float* b_fc  = (const float*)d_in[10];
    float* out = (float*)d_out;

    cudaFuncSetAttribute(rnn_hmma,
                         cudaFuncAttributeMaxDynamicSharedMemorySize, SMEM_BYTES);
    rnn_hmma<<<GRIDN, NTH, SMEM_BYTES>>>(
        x, W_ih0, W_hh0, b_ih0, b_hh0,
        W_ih1, W_hh1, b_ih1, b_hh1, W_fc, b_fc, out);
}